// round 1
// baseline (speedup 1.0000x reference)
#include <cuda_runtime.h>
#include <math.h>

#define BB 4
#define TT 2048
#define CC 1024
#define HH 16
#define DHH 64
#define MROWS (BB*TT)   // 8192

// scratch (allocation-free rule: __device__ globals)
__device__ float g_q[(size_t)BB*HH*TT*DHH];
__device__ float g_k[(size_t)BB*HH*TT*DHH];
__device__ float g_v[(size_t)BB*HH*TT*DHH];
__device__ float g_att[(size_t)BB*TT*CC];

// ---------------------------------------------------------------------------
// Per-head projection GEMM: out[b,h,t,d] = sum_c x[b,t,c] * W[h,c,d] + bias[h,d]
// x: [M=8192, C=1024] row-major. W: [H, C, DH]. out: [B,H,T,DH].
// Tile: BM=64, BN=64(=DH), BK=16. 256 threads, 4x4 microtile.
// ---------------------------------------------------------------------------
__global__ __launch_bounds__(256) void proj_kernel(
    const float* __restrict__ x, const float* __restrict__ W,
    const float* __restrict__ bias, float* __restrict__ out)
{
    const int h  = blockIdx.y;
    const int m0 = blockIdx.x * 64;
    __shared__ float As[16][64];   // As[k][m]
    __shared__ float Bs[16][64];   // Bs[k][n]
    const int tid = threadIdx.x;
    const int tx = tid % 16;       // col group (n)
    const int ty = tid / 16;       // row group (m)
    float acc[4][4] = {};
    const float* Wh = W + (size_t)h * CC * DHH;

    const int ar = tid / 4;            // 0..63 row in A tile
    const int ac = (tid % 4) * 4;      // 0,4,8,12 col in A tile
    const int br = tid / 16;           // 0..15 row in B tile
    const int bc = (tid % 16) * 4;     // 0..60 col

    for (int k0 = 0; k0 < CC; k0 += 16) {
        float4 av = *reinterpret_cast<const float4*>(&x[(size_t)(m0 + ar) * CC + k0 + ac]);
        As[ac + 0][ar] = av.x; As[ac + 1][ar] = av.y;
        As[ac + 2][ar] = av.z; As[ac + 3][ar] = av.w;
        *reinterpret_cast<float4*>(&Bs[br][bc]) =
            *reinterpret_cast<const float4*>(&Wh[(size_t)(k0 + br) * DHH + bc]);
        __syncthreads();
        #pragma unroll
        for (int k = 0; k < 16; k++) {
            float4 a4 = *reinterpret_cast<const float4*>(&As[k][ty * 4]);
            float4 b4 = *reinterpret_cast<const float4*>(&Bs[k][tx * 4]);
            float aa[4] = {a4.x, a4.y, a4.z, a4.w};
            float bb[4] = {b4.x, b4.y, b4.z, b4.w};
            #pragma unroll
            for (int i = 0; i < 4; i++)
                #pragma unroll
                for (int j = 0; j < 4; j++)
                    acc[i][j] += aa[i] * bb[j];
        }
        __syncthreads();
    }
    #pragma unroll
    for (int i = 0; i < 4; i++) {
        int m = m0 + ty * 4 + i;
        int bidx = m / TT, t = m % TT;
        float* orow = out + ((size_t)(bidx * HH + h) * TT + t) * DHH;
        #pragma unroll
        for (int j = 0; j < 4; j++)
            orow[tx * 4 + j] = acc[i][j] + bias[h * DHH + tx * 4 + j];
    }
}

// ---------------------------------------------------------------------------
// Output projection GEMM: out[m, n] = sum_c A[m,c]*Wo[c,n] + bo[n]
// ---------------------------------------------------------------------------
__global__ __launch_bounds__(256) void oproj_kernel(
    const float* __restrict__ A, const float* __restrict__ W,
    const float* __restrict__ bias, float* __restrict__ out)
{
    const int n0 = blockIdx.y * 64;
    const int m0 = blockIdx.x * 64;
    __shared__ float As[16][64];
    __shared__ float Bs[16][64];
    const int tid = threadIdx.x;
    const int tx = tid % 16;
    const int ty = tid / 16;
    float acc[4][4] = {};

    const int ar = tid / 4;
    const int ac = (tid % 4) * 4;
    const int br = tid / 16;
    const int bc = (tid % 16) * 4;

    for (int k0 = 0; k0 < CC; k0 += 16) {
        float4 av = *reinterpret_cast<const float4*>(&A[(size_t)(m0 + ar) * CC + k0 + ac]);
        As[ac + 0][ar] = av.x; As[ac + 1][ar] = av.y;
        As[ac + 2][ar] = av.z; As[ac + 3][ar] = av.w;
        *reinterpret_cast<float4*>(&Bs[br][bc]) =
            *reinterpret_cast<const float4*>(&W[(size_t)(k0 + br) * CC + n0 + bc]);
        __syncthreads();
        #pragma unroll
        for (int k = 0; k < 16; k++) {
            float4 a4 = *reinterpret_cast<const float4*>(&As[k][ty * 4]);
            float4 b4 = *reinterpret_cast<const float4*>(&Bs[k][tx * 4]);
            float aa[4] = {a4.x, a4.y, a4.z, a4.w};
            float bb[4] = {b4.x, b4.y, b4.z, b4.w};
            #pragma unroll
            for (int i = 0; i < 4; i++)
                #pragma unroll
                for (int j = 0; j < 4; j++)
                    acc[i][j] += aa[i] * bb[j];
        }
        __syncthreads();
    }
    #pragma unroll
    for (int i = 0; i < 4; i++) {
        int m = m0 + ty * 4 + i;
        #pragma unroll
        for (int j = 0; j < 4; j++)
            out[(size_t)m * CC + n0 + tx * 4 + j] = acc[i][j] + bias[n0 + tx * 4 + j];
    }
}

// ---------------------------------------------------------------------------
// Causal flash attention, fp32. One thread = one query row.
// CTA: 128 threads = 128 queries. K/V streamed in 64-row tiles through smem.
// All smem reads in the compute loops are warp-uniform (broadcast): free.
// ---------------------------------------------------------------------------
__global__ __launch_bounds__(128, 2) void attn_kernel(
    const float* __restrict__ gq, const float* __restrict__ gk,
    const float* __restrict__ gv, float* __restrict__ gatt)
{
    const int bh  = blockIdx.y;                          // 0..63
    const int qt  = gridDim.x - 1 - blockIdx.x;          // heavy tiles scheduled first
    const int tid = threadIdx.x;
    const int t   = qt * 128 + tid;                      // query index
    const int b   = bh / HH, h = bh % HH;

    __shared__ float Ks[64][64];
    __shared__ float Vs[64][64];

    const float scale = 0.03125f;                        // C^-0.5 = 1/32
    const float* qrow = gq + ((size_t)bh * TT + t) * DHH;

    float q[64], o[64];
    #pragma unroll
    for (int d4 = 0; d4 < 16; d4++) {
        float4 v4 = *reinterpret_cast<const float4*>(&qrow[d4 * 4]);
        q[d4 * 4 + 0] = v4.x * scale; q[d4 * 4 + 1] = v4.y * scale;
        q[d4 * 4 + 2] = v4.z * scale; q[d4 * 4 + 3] = v4.w * scale;
    }
    #pragma unroll
    for (int d = 0; d < 64; d++) o[d] = 0.0f;

    float mval = -INFINITY, l = 0.0f;
    const int kend = (qt + 1) * 128;
    const float* Kb = gk + (size_t)bh * TT * DHH;
    const float* Vb = gv + (size_t)bh * TT * DHH;

    for (int j0 = 0; j0 < kend; j0 += 64) {
        __syncthreads();
        #pragma unroll
        for (int it = 0; it < 8; it++) {
            int idx = it * 128 + tid;                    // float4 index 0..1023
            int r = idx / 16, c4 = (idx % 16) * 4;
            *reinterpret_cast<float4*>(&Ks[r][c4]) =
                *reinterpret_cast<const float4*>(&Kb[(size_t)(j0 + r) * DHH + c4]);
            *reinterpret_cast<float4*>(&Vs[r][c4]) =
                *reinterpret_cast<const float4*>(&Vb[(size_t)(j0 + r) * DHH + c4]);
        }
        __syncthreads();

        float sc[64];
        float tmax = -INFINITY;
        #pragma unroll
        for (int j = 0; j < 64; j++) {
            float s0 = 0.f, s1 = 0.f, s2 = 0.f, s3 = 0.f;
            #pragma unroll
            for (int d4 = 0; d4 < 16; d4++) {
                float4 kv = *reinterpret_cast<const float4*>(&Ks[j][d4 * 4]);
                s0 += q[d4 * 4 + 0] * kv.x;
                s1 += q[d4 * 4 + 1] * kv.y;
                s2 += q[d4 * 4 + 2] * kv.z;
                s3 += q[d4 * 4 + 3] * kv.w;
            }
            float s = (s0 + s1) + (s2 + s3);
            s = (j0 + j <= t) ? s : -INFINITY;
            sc[j] = s;
            tmax = fmaxf(tmax, s);
        }

        float mnew = fmaxf(mval, tmax);
        float corr = __expf(mval - mnew);                // -inf first iter -> 0
        l *= corr;
        #pragma unroll
        for (int d = 0; d < 64; d++) o[d] *= corr;

        #pragma unroll
        for (int j = 0; j < 64; j++) {
            float p = __expf(sc[j] - mnew);              // masked -> exp(-inf)=0
            l += p;
            #pragma unroll
            for (int d4 = 0; d4 < 16; d4++) {
                float4 vv = *reinterpret_cast<const float4*>(&Vs[j][d4 * 4]);
                o[d4 * 4 + 0] += p * vv.x;
                o[d4 * 4 + 1] += p * vv.y;
                o[d4 * 4 + 2] += p * vv.z;
                o[d4 * 4 + 3] += p * vv.w;
            }
        }
        mval = mnew;
    }

    const float inv = 1.0f / l;
    float* orow = gatt + ((size_t)(b * TT + t)) * CC + h * DHH;
    #pragma unroll
    for (int d4 = 0; d4 < 16; d4++) {
        float4 v4;
        v4.x = o[d4 * 4 + 0] * inv; v4.y = o[d4 * 4 + 1] * inv;
        v4.z = o[d4 * 4 + 2] * inv; v4.w = o[d4 * 4 + 3] * inv;
        *reinterpret_cast<float4*>(&orow[d4 * 4]) = v4;
    }
}

extern "C" void kernel_launch(void* const* d_in, const int* in_sizes, int n_in,
                              void* d_out, int out_size) {
    const float* x  = (const float*)d_in[0];
    const float* Wq = (const float*)d_in[1];
    const float* bq = (const float*)d_in[2];
    const float* Wk = (const float*)d_in[3];
    const float* bk = (const float*)d_in[4];
    const float* Wv = (const float*)d_in[5];
    const float* bv = (const float*)d_in[6];
    const float* Wo = (const float*)d_in[7];
    const float* bo = (const float*)d_in[8];
    float* out = (float*)d_out;

    float *qp, *kp, *vp, *ap;
    cudaGetSymbolAddress((void**)&qp, g_q);
    cudaGetSymbolAddress((void**)&kp, g_k);
    cudaGetSymbolAddress((void**)&vp, g_v);
    cudaGetSymbolAddress((void**)&ap, g_att);

    dim3 pgrid(MROWS / 64, HH);
    proj_kernel<<<pgrid, 256>>>(x, Wq, bq, qp);
    proj_kernel<<<pgrid, 256>>>(x, Wk, bk, kp);
    proj_kernel<<<pgrid, 256>>>(x, Wv, bv, vp);

    attn_kernel<<<dim3(TT / 128, BB * HH), 128>>>(qp, kp, vp, ap);

    oproj_kernel<<<dim3(MROWS / 64, CC / 64), 256>>>(ap, Wo, bo, out);
}

// round 3
// speedup vs baseline: 1.4595x; 1.4595x over previous
#include <cuda_runtime.h>
#include <cuda_bf16.h>
#include <math.h>
#include <stdint.h>

#define BB 4
#define TT 2048
#define CC 1024
#define HH 16
#define DHH 64
#define MROWS (BB*TT)     // 8192
#define NQKV (3*CC)       // 3072

// ------------------------------- scratch (no allocs allowed) ----------------
__device__ __nv_bfloat16 g_xh[(size_t)MROWS*CC];
__device__ __nv_bfloat16 g_xl[(size_t)MROWS*CC];
__device__ __nv_bfloat16 g_wth[(size_t)NQKV*CC];
__device__ __nv_bfloat16 g_wtl[(size_t)NQKV*CC];
__device__ __nv_bfloat16 g_woth[(size_t)CC*CC];
__device__ __nv_bfloat16 g_wotl[(size_t)CC*CC];
__device__ float g_bias[NQKV];
__device__ float g_qkv[(size_t)MROWS*NQKV];
__device__ float g_att[(size_t)MROWS*CC];
__device__ __nv_bfloat16 g_ath[(size_t)MROWS*CC];
__device__ __nv_bfloat16 g_atl[(size_t)MROWS*CC];

// ------------------------------- PTX helpers --------------------------------
__device__ __forceinline__ uint32_t smem_u32(const void* p) {
    uint32_t a;
    asm("{ .reg .u64 t; cvta.to.shared.u64 t, %1; cvt.u32.u64 %0, t; }" : "=r"(a) : "l"(p));
    return a;
}
__device__ __forceinline__ void cp16(uint32_t dst, const void* src) {
    asm volatile("cp.async.cg.shared.global [%0], [%1], 16;" :: "r"(dst), "l"(src));
}
__device__ __forceinline__ void ldm_x4(uint32_t* r, uint32_t addr) {
    asm volatile("ldmatrix.sync.aligned.m8n8.x4.shared.b16 {%0,%1,%2,%3}, [%4];"
                 : "=r"(r[0]), "=r"(r[1]), "=r"(r[2]), "=r"(r[3]) : "r"(addr));
}
__device__ __forceinline__ void mma16816(float* d, const uint32_t* a, const uint32_t* b) {
    asm volatile(
        "mma.sync.aligned.m16n8k16.row.col.f32.bf16.bf16.f32 "
        "{%0,%1,%2,%3}, {%4,%5,%6,%7}, {%8,%9}, {%0,%1,%2,%3};"
        : "+f"(d[0]), "+f"(d[1]), "+f"(d[2]), "+f"(d[3])
        : "r"(a[0]), "r"(a[1]), "r"(a[2]), "r"(a[3]), "r"(b[0]), "r"(b[1]));
}

// ------------------------------- conversion ---------------------------------
__global__ __launch_bounds__(256) void conv_split(
    const float4* __restrict__ src, __nv_bfloat162* __restrict__ hi,
    __nv_bfloat162* __restrict__ lo, int n4)
{
    int i = blockIdx.x * blockDim.x + threadIdx.x;
    if (i >= n4) return;
    float4 v = src[i];
    __nv_bfloat16 hx = __float2bfloat16(v.x), hy = __float2bfloat16(v.y);
    __nv_bfloat16 hz = __float2bfloat16(v.z), hw = __float2bfloat16(v.w);
    __nv_bfloat162 h0; h0.x = hx; h0.y = hy;
    __nv_bfloat162 h1; h1.x = hz; h1.y = hw;
    hi[2*i] = h0; hi[2*i+1] = h1;
    __nv_bfloat162 l0, l1;
    l0.x = __float2bfloat16(v.x - __bfloat162float(hx));
    l0.y = __float2bfloat16(v.y - __bfloat162float(hy));
    l1.x = __float2bfloat16(v.z - __bfloat162float(hz));
    l1.y = __float2bfloat16(v.w - __bfloat162float(hw));
    lo[2*i] = l0; lo[2*i+1] = l1;
}

// repack Wq/Wk/Wv [H,C,DH] -> Wt[N=3072][K=1024] (K contiguous), hi/lo + bias
__global__ __launch_bounds__(256) void repack_qkv(
    const float* __restrict__ Wq, const float* __restrict__ Wk, const float* __restrict__ Wv,
    const float* __restrict__ bq, const float* __restrict__ bk, const float* __restrict__ bv)
{
    int n = blockIdx.x;                    // 0..3071
    int p = n >> 10, w = n & 1023;
    int h = w >> 6, d = w & 63;
    const float* W = (p == 0) ? Wq : (p == 1) ? Wk : Wv;
    const float* bsrc = (p == 0) ? bq : (p == 1) ? bk : bv;
    for (int c = threadIdx.x; c < CC; c += 256) {
        float v = W[((size_t)h * CC + c) * DHH + d];
        __nv_bfloat16 hv = __float2bfloat16(v);
        g_wth[(size_t)n * CC + c] = hv;
        g_wtl[(size_t)n * CC + c] = __float2bfloat16(v - __bfloat162float(hv));
    }
    if (threadIdx.x == 0) g_bias[n] = bsrc[w];
}

// repack Wo [C,C] -> Wot[N=1024][K=1024] hi/lo (transpose)
__global__ __launch_bounds__(256) void repack_wo(const float* __restrict__ Wo)
{
    int n = blockIdx.x;
    for (int c = threadIdx.x; c < CC; c += 256) {
        float v = Wo[(size_t)c * CC + n];
        __nv_bfloat16 hv = __float2bfloat16(v);
        g_woth[(size_t)n * CC + c] = hv;
        g_wotl[(size_t)n * CC + c] = __float2bfloat16(v - __bfloat162float(hv));
    }
}

// ------------------------------- mma.sync GEMM ------------------------------
// C[m0:+128, n0:+128] = Ah@Bh^T + Ah@Bl^T + Al@Bh^T + bias
// A: [M x CC] bf16 hi/lo rows m; B: [N x CC] bf16 hi/lo rows n (K contiguous).
#define KCH 32
#define NCH (CC / KCH)        // 32 chunks
#define TILE8K 8192           // 128 rows x 32 k x 2B
#define GSTAGE (4 * TILE8K)   // 32 KB
#define SMEM_GEMM (2 * GSTAGE)

__global__ void __launch_bounds__(256, 1) gemm_bf16x3(
    const __nv_bfloat16* __restrict__ Ah, const __nv_bfloat16* __restrict__ Al,
    const __nv_bfloat16* __restrict__ Bh, const __nv_bfloat16* __restrict__ Bl,
    const float* __restrict__ bias, float* __restrict__ C, int ldc)
{
    extern __shared__ char dsm[];
    const uint32_t sbase = smem_u32(dsm);
    const int tid = threadIdx.x;
    const int l   = tid & 31;
    const int wid = tid >> 5;
    const int wm  = wid & 1;        // 2 m-blocks of 64
    const int wn  = wid >> 1;       // 4 n-blocks of 32
    const int m0  = blockIdx.x * 128;
    const int n0  = blockIdx.y * 128;

    // per-thread cp.async descriptors: 8 granules of 16B per chunk
    const __nv_bfloat16* gptr[8];
    uint32_t soff[8];
    {
        const __nv_bfloat16* bases[4] = {Ah, Al, Bh, Bl};
        #pragma unroll
        for (int it = 0; it < 8; ++it) {
            int g = it * 256 + tid;         // 0..2047
            int tile = g >> 9;              // 0..3
            int r = (g >> 2) & 127;
            int slot = g & 3;               // 16B slot within 64B row
            int row0 = (tile < 2) ? m0 : n0;
            gptr[it] = bases[tile] + (size_t)(row0 + r) * CC + slot * 8;
            soff[it] = sbase + tile * TILE8K + r * 64 + ((slot ^ ((r >> 1) & 3)) << 4);
        }
    }

    // ldmatrix per-lane row bases (swizzled layout: off = row*64 + (slot^((row>>1)&3))*16)
    const int hA = l >> 4;                       // A: k-half select
    const int rAl = wm * 64 + (l & 15);
    uint32_t a64[4]; int ax[4];
    #pragma unroll
    for (int i = 0; i < 4; ++i) { int rr = rAl + i * 16; a64[i] = rr * 64; ax[i] = (rr >> 1) & 3; }
    const int hB = (l >> 3) & 1;                 // B: k-half select
    const int rBl = wn * 32 + ((l & 7) | ((l >> 4) << 3));
    uint32_t b64[2]; int bx[2];
    #pragma unroll
    for (int j = 0; j < 2; ++j) { int rr = rBl + j * 16; b64[j] = rr * 64; bx[j] = (rr >> 1) & 3; }

    float acc[4][4][4] = {};

    // prologue: load chunk 0 into stage 0
    #pragma unroll
    for (int it = 0; it < 8; ++it) cp16(soff[it], gptr[it]);
    asm volatile("cp.async.commit_group;" ::: "memory");

    for (int c = 0; c < NCH; ++c) {
        const uint32_t st = sbase + (c & 1) * GSTAGE;
        if (c + 1 < NCH) {
            const uint32_t nb = ((c + 1) & 1) * GSTAGE;
            const int kadv = (c + 1) * KCH;
            #pragma unroll
            for (int it = 0; it < 8; ++it) cp16(soff[it] + nb, gptr[it] + kadv);
            asm volatile("cp.async.commit_group;" ::: "memory");
            asm volatile("cp.async.wait_group 1;" ::: "memory");
        } else {
            asm volatile("cp.async.wait_group 0;" ::: "memory");
        }
        __syncthreads();

        const uint32_t sAh = st, sAl = st + TILE8K, sBh = st + 2 * TILE8K, sBl = st + 3 * TILE8K;
        #pragma unroll
        for (int ks = 0; ks < 2; ++ks) {
            const int slA = ks * 2 + hA;
            const int slB = ks * 2 + hB;
            uint32_t ah[4][4], al_[4][4], bh[4][2], bl[4][2];
            #pragma unroll
            for (int i = 0; i < 4; ++i) {
                ldm_x4(ah[i],  sAh + a64[i] + (uint32_t)((slA ^ ax[i]) << 4));
                ldm_x4(al_[i], sAl + a64[i] + (uint32_t)((slA ^ ax[i]) << 4));
            }
            #pragma unroll
            for (int j = 0; j < 2; ++j) {
                uint32_t t[4];
                ldm_x4(t, sBh + b64[j] + (uint32_t)((slB ^ bx[j]) << 4));
                bh[2*j][0] = t[0]; bh[2*j][1] = t[1]; bh[2*j+1][0] = t[2]; bh[2*j+1][1] = t[3];
                ldm_x4(t, sBl + b64[j] + (uint32_t)((slB ^ bx[j]) << 4));
                bl[2*j][0] = t[0]; bl[2*j][1] = t[1]; bl[2*j+1][0] = t[2]; bl[2*j+1][1] = t[3];
            }
            #pragma unroll
            for (int i = 0; i < 4; ++i)
                #pragma unroll
                for (int j = 0; j < 4; ++j) {
                    mma16816(acc[i][j], ah[i],  bh[j]);
                    mma16816(acc[i][j], ah[i],  bl[j]);
                    mma16816(acc[i][j], al_[i], bh[j]);
                }
        }
        __syncthreads();
    }

    // epilogue: bias + store
    #pragma unroll
    for (int i = 0; i < 4; ++i) {
        const int m = m0 + wm * 64 + i * 16 + (l >> 2);
        #pragma unroll
        for (int j = 0; j < 4; ++j) {
            const int n = n0 + wn * 32 + j * 8 + 2 * (l & 3);
            const float b0 = bias[n], b1 = bias[n + 1];
            float2 v0 = { acc[i][j][0] + b0, acc[i][j][1] + b1 };
            float2 v1 = { acc[i][j][2] + b0, acc[i][j][3] + b1 };
            *reinterpret_cast<float2*>(&C[(size_t)m * ldc + n]) = v0;
            *reinterpret_cast<float2*>(&C[(size_t)(m + 8) * ldc + n]) = v1;
        }
    }
}

// ------------------------------- attention (fp32) ---------------------------
// qkv layout: [B*T, 3072]; q at col h*64, k at 1024+h*64, v at 2048+h*64
__global__ __launch_bounds__(128, 2) void attn_kernel(
    const float* __restrict__ qkv, float* __restrict__ gatt)
{
    const int bh  = blockIdx.y;
    const int qt  = gridDim.x - 1 - blockIdx.x;
    const int tid = threadIdx.x;
    const int t   = qt * 128 + tid;
    const int b   = bh / HH, h = bh % HH;

    __shared__ float Ks[64][64];
    __shared__ float Vs[64][64];

    const float scale = 0.03125f;
    const float* qrow = qkv + ((size_t)(b * TT + t)) * NQKV + h * DHH;

    float q[64], o[64];
    #pragma unroll
    for (int d4 = 0; d4 < 16; d4++) {
        float4 v4 = *reinterpret_cast<const float4*>(&qrow[d4 * 4]);
        q[d4 * 4 + 0] = v4.x * scale; q[d4 * 4 + 1] = v4.y * scale;
        q[d4 * 4 + 2] = v4.z * scale; q[d4 * 4 + 3] = v4.w * scale;
    }
    #pragma unroll
    for (int d = 0; d < 64; d++) o[d] = 0.0f;

    float mval = -INFINITY, lsum = 0.0f;
    const int kend = (qt + 1) * 128;
    const float* Kb = qkv + (size_t)b * TT * NQKV + CC + h * DHH;
    const float* Vb = qkv + (size_t)b * TT * NQKV + 2 * CC + h * DHH;

    for (int j0 = 0; j0 < kend; j0 += 64) {
        __syncthreads();
        #pragma unroll
        for (int it = 0; it < 8; it++) {
            int idx = it * 128 + tid;
            int r = idx / 16, c4 = (idx % 16) * 4;
            *reinterpret_cast<float4*>(&Ks[r][c4]) =
                *reinterpret_cast<const float4*>(&Kb[(size_t)(j0 + r) * NQKV + c4]);
            *reinterpret_cast<float4*>(&Vs[r][c4]) =
                *reinterpret_cast<const float4*>(&Vb[(size_t)(j0 + r) * NQKV + c4]);
        }
        __syncthreads();

        float sc[64];
        float tmax = -INFINITY;
        #pragma unroll
        for (int j = 0; j < 64; j++) {
            float s0 = 0.f, s1 = 0.f, s2 = 0.f, s3 = 0.f;
            #pragma unroll
            for (int d4 = 0; d4 < 16; d4++) {
                float4 kv = *reinterpret_cast<const float4*>(&Ks[j][d4 * 4]);
                s0 += q[d4 * 4 + 0] * kv.x;
                s1 += q[d4 * 4 + 1] * kv.y;
                s2 += q[d4 * 4 + 2] * kv.z;
                s3 += q[d4 * 4 + 3] * kv.w;
            }
            float s = (s0 + s1) + (s2 + s3);
            s = (j0 + j <= t) ? s : -INFINITY;
            sc[j] = s;
            tmax = fmaxf(tmax, s);
        }

        float mnew = fmaxf(mval, tmax);
        float corr = __expf(mval - mnew);
        lsum *= corr;
        #pragma unroll
        for (int d = 0; d < 64; d++) o[d] *= corr;

        #pragma unroll
        for (int j = 0; j < 64; j++) {
            float p = __expf(sc[j] - mnew);
            lsum += p;
            #pragma unroll
            for (int d4 = 0; d4 < 16; d4++) {
                float4 vv = *reinterpret_cast<const float4*>(&Vs[j][d4 * 4]);
                o[d4 * 4 + 0] += p * vv.x;
                o[d4 * 4 + 1] += p * vv.y;
                o[d4 * 4 + 2] += p * vv.z;
                o[d4 * 4 + 3] += p * vv.w;
            }
        }
        mval = mnew;
    }

    const float inv = 1.0f / lsum;
    float* orow = gatt + ((size_t)(b * TT + t)) * CC + h * DHH;
    #pragma unroll
    for (int d4 = 0; d4 < 16; d4++) {
        float4 v4;
        v4.x = o[d4 * 4 + 0] * inv; v4.y = o[d4 * 4 + 1] * inv;
        v4.z = o[d4 * 4 + 2] * inv; v4.w = o[d4 * 4 + 3] * inv;
        *reinterpret_cast<float4*>(&orow[d4 * 4]) = v4;
    }
}

// ------------------------------- launch -------------------------------------
extern "C" void kernel_launch(void* const* d_in, const int* in_sizes, int n_in,
                              void* d_out, int out_size) {
    const float* x  = (const float*)d_in[0];
    const float* Wq = (const float*)d_in[1];
    const float* bq = (const float*)d_in[2];
    const float* Wk = (const float*)d_in[3];
    const float* bk = (const float*)d_in[4];
    const float* Wv = (const float*)d_in[5];
    const float* bv = (const float*)d_in[6];
    const float* Wo = (const float*)d_in[7];
    const float* bo = (const float*)d_in[8];
    float* out = (float*)d_out;

    static int once = 0;
    if (!once) {
        cudaFuncSetAttribute(gemm_bf16x3, cudaFuncAttributeMaxDynamicSharedMemorySize, SMEM_GEMM);
        once = 1;
    }

    float *qkvp, *attp, *biasp;
    __nv_bfloat16 *xh, *xl, *wth, *wtl, *woth, *wotl, *ath, *atl;
    cudaGetSymbolAddress((void**)&xh, g_xh);
    cudaGetSymbolAddress((void**)&xl, g_xl);
    cudaGetSymbolAddress((void**)&wth, g_wth);
    cudaGetSymbolAddress((void**)&wtl, g_wtl);
    cudaGetSymbolAddress((void**)&woth, g_woth);
    cudaGetSymbolAddress((void**)&wotl, g_wotl);
    cudaGetSymbolAddress((void**)&biasp, g_bias);
    cudaGetSymbolAddress((void**)&qkvp, g_qkv);
    cudaGetSymbolAddress((void**)&attp, g_att);
    cudaGetSymbolAddress((void**)&ath, g_ath);
    cudaGetSymbolAddress((void**)&atl, g_atl);

    int n4 = MROWS * CC / 4;
    conv_split<<<n4 / 256, 256>>>((const float4*)x, (__nv_bfloat162*)xh, (__nv_bfloat162*)xl, n4);
    repack_qkv<<<NQKV, 256>>>(Wq, Wk, Wv, bq, bk, bv);
    repack_wo<<<CC, 256>>>(Wo);

    gemm_bf16x3<<<dim3(MROWS / 128, NQKV / 128), 256, SMEM_GEMM>>>(
        xh, xl, wth, wtl, biasp, qkvp, NQKV);

    attn_kernel<<<dim3(TT / 128, BB * HH), 128>>>(qkvp, attp);

    conv_split<<<n4 / 256, 256>>>((const float4*)attp, (__nv_bfloat162*)ath, (__nv_bfloat162*)atl, n4);

    gemm_bf16x3<<<dim3(MROWS / 128, CC / 128), 256, SMEM_GEMM>>>(
        ath, atl, woth, wotl, bo, out, CC);
}

// round 4
// speedup vs baseline: 4.8014x; 3.2898x over previous
#include <cuda_runtime.h>
#include <cuda_bf16.h>
#include <math.h>
#include <stdint.h>

#define BB 4
#define TT 2048
#define CC 1024
#define HH 16
#define DHH 64
#define MROWS (BB*TT)     // 8192
#define NQKV (3*CC)       // 3072

// ------------------------------- scratch (no allocs allowed) ----------------
__device__ __nv_bfloat16 g_xh[(size_t)MROWS*CC];
__device__ __nv_bfloat16 g_xl[(size_t)MROWS*CC];
__device__ __nv_bfloat16 g_wth[(size_t)NQKV*CC];
__device__ __nv_bfloat16 g_wtl[(size_t)NQKV*CC];
__device__ __nv_bfloat16 g_woth[(size_t)CC*CC];
__device__ __nv_bfloat16 g_wotl[(size_t)CC*CC];
__device__ float g_bias[NQKV];
__device__ float g_qkv[(size_t)MROWS*NQKV];
__device__ __nv_bfloat16 g_ath[(size_t)MROWS*CC];
__device__ __nv_bfloat16 g_atl[(size_t)MROWS*CC];

// ------------------------------- PTX helpers --------------------------------
__device__ __forceinline__ uint32_t smem_u32(const void* p) {
    uint32_t a;
    asm("{ .reg .u64 t; cvta.to.shared.u64 t, %1; cvt.u32.u64 %0, t; }" : "=r"(a) : "l"(p));
    return a;
}
__device__ __forceinline__ void cp16(uint32_t dst, const void* src) {
    asm volatile("cp.async.cg.shared.global [%0], [%1], 16;" :: "r"(dst), "l"(src));
}
__device__ __forceinline__ void ldm_x4(uint32_t* r, uint32_t addr) {
    asm volatile("ldmatrix.sync.aligned.m8n8.x4.shared.b16 {%0,%1,%2,%3}, [%4];"
                 : "=r"(r[0]), "=r"(r[1]), "=r"(r[2]), "=r"(r[3]) : "r"(addr));
}
__device__ __forceinline__ void mma16816(float* d, const uint32_t* a, const uint32_t* b) {
    asm volatile(
        "mma.sync.aligned.m16n8k16.row.col.f32.bf16.bf16.f32 "
        "{%0,%1,%2,%3}, {%4,%5,%6,%7}, {%8,%9}, {%0,%1,%2,%3};"
        : "+f"(d[0]), "+f"(d[1]), "+f"(d[2]), "+f"(d[3])
        : "r"(a[0]), "r"(a[1]), "r"(a[2]), "r"(a[3]), "r"(b[0]), "r"(b[1]));
}
// pack two fp32 -> bf16x2 (v0 in low half)
__device__ __forceinline__ uint32_t pack_bf16(float v0, float v1) {
    uint32_t r;
    asm("cvt.rn.bf16x2.f32 %0, %1, %2;" : "=r"(r) : "f"(v1), "f"(v0));
    return r;
}
// split pair: returns hi pack, computes lo pack
__device__ __forceinline__ void split_pair(float v0, float v1, uint32_t& hp, uint32_t& lp) {
    hp = pack_bf16(v0, v1);
    float h0 = __uint_as_float(hp << 16);
    float h1 = __uint_as_float(hp & 0xFFFF0000u);
    lp = pack_bf16(v0 - h0, v1 - h1);
}

// ------------------------------- conversion ---------------------------------
__global__ __launch_bounds__(256) void conv_split(
    const float4* __restrict__ src, __nv_bfloat162* __restrict__ hi,
    __nv_bfloat162* __restrict__ lo, int n4)
{
    int i = blockIdx.x * blockDim.x + threadIdx.x;
    if (i >= n4) return;
    float4 v = src[i];
    uint32_t h0, l0, h1, l1;
    split_pair(v.x, v.y, h0, l0);
    split_pair(v.z, v.w, h1, l1);
    ((uint32_t*)hi)[2*i] = h0; ((uint32_t*)hi)[2*i+1] = h1;
    ((uint32_t*)lo)[2*i] = l0; ((uint32_t*)lo)[2*i+1] = l1;
}

__global__ __launch_bounds__(256) void repack_qkv(
    const float* __restrict__ Wq, const float* __restrict__ Wk, const float* __restrict__ Wv,
    const float* __restrict__ bq, const float* __restrict__ bk, const float* __restrict__ bv)
{
    int n = blockIdx.x;                    // 0..3071
    int p = n >> 10, w = n & 1023;
    int h = w >> 6, d = w & 63;
    const float* W = (p == 0) ? Wq : (p == 1) ? Wk : Wv;
    const float* bsrc = (p == 0) ? bq : (p == 1) ? bk : bv;
    for (int c = threadIdx.x; c < CC; c += 256) {
        float v = W[((size_t)h * CC + c) * DHH + d];
        __nv_bfloat16 hv = __float2bfloat16(v);
        g_wth[(size_t)n * CC + c] = hv;
        g_wtl[(size_t)n * CC + c] = __float2bfloat16(v - __bfloat162float(hv));
    }
    if (threadIdx.x == 0) g_bias[n] = bsrc[w];
}

__global__ __launch_bounds__(256) void repack_wo(const float* __restrict__ Wo)
{
    int n = blockIdx.x;
    for (int c = threadIdx.x; c < CC; c += 256) {
        float v = Wo[(size_t)c * CC + n];
        __nv_bfloat16 hv = __float2bfloat16(v);
        g_woth[(size_t)n * CC + c] = hv;
        g_wotl[(size_t)n * CC + c] = __float2bfloat16(v - __bfloat162float(hv));
    }
}

// ------------------------------- mma.sync GEMM ------------------------------
#define KCH 32
#define NCH (CC / KCH)        // 32 chunks
#define TILE8K 8192
#define GSTAGE (4 * TILE8K)   // 32 KB
#define SMEM_GEMM (2 * GSTAGE)

__global__ void __launch_bounds__(256, 1) gemm_bf16x3(
    const __nv_bfloat16* __restrict__ Ah, const __nv_bfloat16* __restrict__ Al,
    const __nv_bfloat16* __restrict__ Bh, const __nv_bfloat16* __restrict__ Bl,
    const float* __restrict__ bias, float* __restrict__ C, int ldc)
{
    extern __shared__ char dsm[];
    const uint32_t sbase = smem_u32(dsm);
    const int tid = threadIdx.x;
    const int l   = tid & 31;
    const int wid = tid >> 5;
    const int wm  = wid & 1;
    const int wn  = wid >> 1;
    const int m0  = blockIdx.x * 128;
    const int n0  = blockIdx.y * 128;

    const __nv_bfloat16* gptr[8];
    uint32_t soff[8];
    {
        const __nv_bfloat16* bases[4] = {Ah, Al, Bh, Bl};
        #pragma unroll
        for (int it = 0; it < 8; ++it) {
            int g = it * 256 + tid;
            int tile = g >> 9;
            int r = (g >> 2) & 127;
            int slot = g & 3;
            int row0 = (tile < 2) ? m0 : n0;
            gptr[it] = bases[tile] + (size_t)(row0 + r) * CC + slot * 8;
            soff[it] = sbase + tile * TILE8K + r * 64 + ((slot ^ ((r >> 1) & 3)) << 4);
        }
    }

    const int hA = l >> 4;
    const int rAl = wm * 64 + (l & 15);
    uint32_t a64[4]; int ax[4];
    #pragma unroll
    for (int i = 0; i < 4; ++i) { int rr = rAl + i * 16; a64[i] = rr * 64; ax[i] = (rr >> 1) & 3; }
    const int hB = (l >> 3) & 1;
    const int rBl = wn * 32 + ((l & 7) | ((l >> 4) << 3));
    uint32_t b64[2]; int bx[2];
    #pragma unroll
    for (int j = 0; j < 2; ++j) { int rr = rBl + j * 16; b64[j] = rr * 64; bx[j] = (rr >> 1) & 3; }

    float acc[4][4][4] = {};

    #pragma unroll
    for (int it = 0; it < 8; ++it) cp16(soff[it], gptr[it]);
    asm volatile("cp.async.commit_group;" ::: "memory");

    for (int c = 0; c < NCH; ++c) {
        const uint32_t st = sbase + (c & 1) * GSTAGE;
        if (c + 1 < NCH) {
            const uint32_t nb = ((c + 1) & 1) * GSTAGE;
            const int kadv = (c + 1) * KCH;
            #pragma unroll
            for (int it = 0; it < 8; ++it) cp16(soff[it] + nb, gptr[it] + kadv);
            asm volatile("cp.async.commit_group;" ::: "memory");
            asm volatile("cp.async.wait_group 1;" ::: "memory");
        } else {
            asm volatile("cp.async.wait_group 0;" ::: "memory");
        }
        __syncthreads();

        const uint32_t sAh = st, sAl = st + TILE8K, sBh = st + 2 * TILE8K, sBl = st + 3 * TILE8K;
        #pragma unroll
        for (int ks = 0; ks < 2; ++ks) {
            const int slA = ks * 2 + hA;
            const int slB = ks * 2 + hB;
            uint32_t ah[4][4], al_[4][4], bh[4][2], bl[4][2];
            #pragma unroll
            for (int i = 0; i < 4; ++i) {
                ldm_x4(ah[i],  sAh + a64[i] + (uint32_t)((slA ^ ax[i]) << 4));
                ldm_x4(al_[i], sAl + a64[i] + (uint32_t)((slA ^ ax[i]) << 4));
            }
            #pragma unroll
            for (int j = 0; j < 2; ++j) {
                uint32_t t[4];
                ldm_x4(t, sBh + b64[j] + (uint32_t)((slB ^ bx[j]) << 4));
                bh[2*j][0] = t[0]; bh[2*j][1] = t[1]; bh[2*j+1][0] = t[2]; bh[2*j+1][1] = t[3];
                ldm_x4(t, sBl + b64[j] + (uint32_t)((slB ^ bx[j]) << 4));
                bl[2*j][0] = t[0]; bl[2*j][1] = t[1]; bl[2*j+1][0] = t[2]; bl[2*j+1][1] = t[3];
            }
            #pragma unroll
            for (int i = 0; i < 4; ++i)
                #pragma unroll
                for (int j = 0; j < 4; ++j) {
                    mma16816(acc[i][j], ah[i],  bh[j]);
                    mma16816(acc[i][j], ah[i],  bl[j]);
                    mma16816(acc[i][j], al_[i], bh[j]);
                }
        }
        __syncthreads();
    }

    #pragma unroll
    for (int i = 0; i < 4; ++i) {
        const int m = m0 + wm * 64 + i * 16 + (l >> 2);
        #pragma unroll
        for (int j = 0; j < 4; ++j) {
            const int n = n0 + wn * 32 + j * 8 + 2 * (l & 3);
            const float b0 = bias[n], b1 = bias[n + 1];
            float2 v0 = { acc[i][j][0] + b0, acc[i][j][1] + b1 };
            float2 v1 = { acc[i][j][2] + b0, acc[i][j][3] + b1 };
            *reinterpret_cast<float2*>(&C[(size_t)m * ldc + n]) = v0;
            *reinterpret_cast<float2*>(&C[(size_t)(m + 8) * ldc + n]) = v1;
        }
    }
}

// ------------------------------- mma flash attention ------------------------
// smem (32KB), two phases:
//  phase Q:  Qh[128 rows][128B], Ql at +16384
//  phase KV: Kh[64][128B] @0, Kl @8192, Vth[64 dims][128B] @16384, Vtl @24576
#define AKH 0
#define AKL 8192
#define AVH 16384
#define AVL 24576
#define AQL 16384

__global__ void __launch_bounds__(256, 1) attn_mma(
    const float* __restrict__ qkv,
    __nv_bfloat16* __restrict__ ath, __nv_bfloat16* __restrict__ atl)
{
    __shared__ char smem[32768];
    const uint32_t sb = smem_u32(smem);
    const int tid = threadIdx.x;
    const int l   = tid & 31;
    const int wq  = tid >> 5;              // warp id: 16 queries each
    const int bh  = blockIdx.y;
    const int b   = bh >> 4, h = bh & 15;
    const int qt  = gridDim.x - 1 - blockIdx.x;
    const int q0  = qt * 128;

    const float scale = 0.03125f;
    const float* qg = qkv + ((size_t)(b * TT + q0)) * NQKV + h * DHH;
    const float* kg = qkv + ((size_t)(b * TT)) * NQKV + CC + h * DHH;
    const float* vg = qkv + ((size_t)(b * TT)) * NQKV + 2 * CC + h * DHH;

    // ---- load Q, scale, split, store smem ----
    #pragma unroll
    for (int it = 0; it < 4; ++it) {
        int id = it * 256 + tid;
        int row = id >> 3, sl = id & 7;
        float4 a = *reinterpret_cast<const float4*>(qg + (size_t)row * NQKV + sl * 8);
        float4 c = *reinterpret_cast<const float4*>(qg + (size_t)row * NQKV + sl * 8 + 4);
        a.x *= scale; a.y *= scale; a.z *= scale; a.w *= scale;
        c.x *= scale; c.y *= scale; c.z *= scale; c.w *= scale;
        uint32_t hb[4], lb[4];
        split_pair(a.x, a.y, hb[0], lb[0]);
        split_pair(a.z, a.w, hb[1], lb[1]);
        split_pair(c.x, c.y, hb[2], lb[2]);
        split_pair(c.z, c.w, hb[3], lb[3]);
        uint32_t off = (uint32_t)(row * 128 + ((sl ^ (row & 7)) << 4));
        *reinterpret_cast<uint4*>(smem + off)       = make_uint4(hb[0], hb[1], hb[2], hb[3]);
        *reinterpret_cast<uint4*>(smem + AQL + off) = make_uint4(lb[0], lb[1], lb[2], lb[3]);
    }
    __syncthreads();

    // ---- ldmatrix Q fragments ----
    uint32_t qh[4][4], ql_[4][4];
    {
        int row = wq * 16 + (l & 15);
        uint32_t rbase = (uint32_t)(row * 128);
        int rx = row & 7;
        #pragma unroll
        for (int kb = 0; kb < 4; ++kb) {
            int s = kb * 2 + (l >> 4);
            uint32_t off = rbase + (uint32_t)((s ^ rx) << 4);
            ldm_x4(qh[kb],  sb + off);
            ldm_x4(ql_[kb], sb + AQL + off);
        }
    }
    __syncthreads();   // Q smem free; reuse for KV

    // ---- accumulators ----
    float o[8][4] = {};
    float m0 = -INFINITY, m1 = -INFINITY, ls0 = 0.f, ls1 = 0.f;
    const int ntiles = 2 * (qt + 1);

    // prefetch regs
    float kf[2][8];
    float vf[2][2][4];
    // prologue: tile 0
    #pragma unroll
    for (int it = 0; it < 2; ++it) {
        int id = it * 256 + tid;
        int kr = id >> 3, ks = id & 7;
        *reinterpret_cast<float4*>(&kf[it][0]) =
            *reinterpret_cast<const float4*>(kg + (size_t)kr * NQKV + ks * 8);
        *reinterpret_cast<float4*>(&kf[it][4]) =
            *reinterpret_cast<const float4*>(kg + (size_t)kr * NQKV + ks * 8 + 4);
        int p = id & 31, d4 = id >> 5;
        *reinterpret_cast<float4*>(&vf[it][0][0]) =
            *reinterpret_cast<const float4*>(vg + (size_t)(2 * p) * NQKV + d4 * 4);
        *reinterpret_cast<float4*>(&vf[it][1][0]) =
            *reinterpret_cast<const float4*>(vg + (size_t)(2 * p + 1) * NQKV + d4 * 4);
    }

    const int qr0 = q0 + wq * 16 + (l >> 2);
    const int qr1 = qr0 + 8;

    for (int ti = 0; ti < ntiles; ++ti) {
        const int j0 = ti * 64;
        __syncthreads();
        // ---- convert prefetch regs -> smem ----
        #pragma unroll
        for (int it = 0; it < 2; ++it) {
            int id = it * 256 + tid;
            int kr = id >> 3, ks = id & 7;
            uint32_t hb[4], lb[4];
            #pragma unroll
            for (int qd = 0; qd < 4; ++qd)
                split_pair(kf[it][2 * qd], kf[it][2 * qd + 1], hb[qd], lb[qd]);
            uint32_t off = (uint32_t)(kr * 128 + ((ks ^ (kr & 7)) << 4));
            *reinterpret_cast<uint4*>(smem + AKH + off) = make_uint4(hb[0], hb[1], hb[2], hb[3]);
            *reinterpret_cast<uint4*>(smem + AKL + off) = make_uint4(lb[0], lb[1], lb[2], lb[3]);
            int p = id & 31, d4 = id >> 5;
            #pragma unroll
            for (int d = 0; d < 4; ++d) {
                uint32_t hp, lp;
                split_pair(vf[it][0][d], vf[it][1][d], hp, lp);
                int drow = d4 * 4 + d;
                uint32_t off2 = (uint32_t)(drow * 128 + (((p >> 2) ^ (drow & 7)) << 4) + (p & 3) * 4);
                *reinterpret_cast<uint32_t*>(smem + AVH + off2) = hp;
                *reinterpret_cast<uint32_t*>(smem + AVL + off2) = lp;
            }
        }
        __syncthreads();

        // ---- prefetch next tile ----
        if (ti + 1 < ntiles) {
            const int jn = j0 + 64;
            #pragma unroll
            for (int it = 0; it < 2; ++it) {
                int id = it * 256 + tid;
                int kr = id >> 3, ks = id & 7;
                *reinterpret_cast<float4*>(&kf[it][0]) =
                    *reinterpret_cast<const float4*>(kg + (size_t)(jn + kr) * NQKV + ks * 8);
                *reinterpret_cast<float4*>(&kf[it][4]) =
                    *reinterpret_cast<const float4*>(kg + (size_t)(jn + kr) * NQKV + ks * 8 + 4);
                int p = id & 31, d4 = id >> 5;
                *reinterpret_cast<float4*>(&vf[it][0][0]) =
                    *reinterpret_cast<const float4*>(vg + (size_t)(jn + 2 * p) * NQKV + d4 * 4);
                *reinterpret_cast<float4*>(&vf[it][1][0]) =
                    *reinterpret_cast<const float4*>(vg + (size_t)(jn + 2 * p + 1) * NQKV + d4 * 4);
            }
        }

        // ---- S = Q K^T (3-pass) ----
        float s[8][4] = {};
        {
            int rbl = (l >> 4) * 8 + (l & 7);
            int sbit = (l >> 3) & 1;
            #pragma unroll
            for (int nbp = 0; nbp < 4; ++nbp) {
                int row = nbp * 16 + rbl;
                uint32_t rbase = (uint32_t)(row * 128);
                int rx = row & 7;
                #pragma unroll
                for (int kb = 0; kb < 4; ++kb) {
                    int sl = kb * 2 + sbit;
                    uint32_t off = rbase + (uint32_t)((sl ^ rx) << 4);
                    uint32_t bh4[4], bl4[4];
                    ldm_x4(bh4, sb + AKH + off);
                    ldm_x4(bl4, sb + AKL + off);
                    mma16816(s[2 * nbp],     qh[kb],  bh4);
                    mma16816(s[2 * nbp],     qh[kb],  bl4);
                    mma16816(s[2 * nbp],     ql_[kb], bh4);
                    mma16816(s[2 * nbp + 1], qh[kb],  bh4 + 2);
                    mma16816(s[2 * nbp + 1], qh[kb],  bl4 + 2);
                    mma16816(s[2 * nbp + 1], ql_[kb], bh4 + 2);
                }
            }
        }

        // ---- causal mask (only last two tiles) ----
        if (j0 >= q0) {
            #pragma unroll
            for (int nb = 0; nb < 8; ++nb) {
                int k0i = j0 + nb * 8 + 2 * (l & 3);
                if (k0i     > qr0) s[nb][0] = -INFINITY;
                if (k0i + 1 > qr0) s[nb][1] = -INFINITY;
                if (k0i     > qr1) s[nb][2] = -INFINITY;
                if (k0i + 1 > qr1) s[nb][3] = -INFINITY;
            }
        }

        // ---- online softmax ----
        float mx0 = -INFINITY, mx1 = -INFINITY;
        #pragma unroll
        for (int nb = 0; nb < 8; ++nb) {
            mx0 = fmaxf(mx0, fmaxf(s[nb][0], s[nb][1]));
            mx1 = fmaxf(mx1, fmaxf(s[nb][2], s[nb][3]));
        }
        mx0 = fmaxf(mx0, __shfl_xor_sync(0xffffffffu, mx0, 1));
        mx0 = fmaxf(mx0, __shfl_xor_sync(0xffffffffu, mx0, 2));
        mx1 = fmaxf(mx1, __shfl_xor_sync(0xffffffffu, mx1, 1));
        mx1 = fmaxf(mx1, __shfl_xor_sync(0xffffffffu, mx1, 2));
        float nm0 = fmaxf(m0, mx0), nm1 = fmaxf(m1, mx1);
        float c0 = __expf(m0 - nm0), c1 = __expf(m1 - nm1);
        ls0 *= c0; ls1 *= c1;
        #pragma unroll
        for (int db = 0; db < 8; ++db) {
            o[db][0] *= c0; o[db][1] *= c0;
            o[db][2] *= c1; o[db][3] *= c1;
        }
        float r0 = 0.f, r1 = 0.f;
        #pragma unroll
        for (int nb = 0; nb < 8; ++nb) {
            s[nb][0] = __expf(s[nb][0] - nm0);
            s[nb][1] = __expf(s[nb][1] - nm0);
            s[nb][2] = __expf(s[nb][2] - nm1);
            s[nb][3] = __expf(s[nb][3] - nm1);
            r0 += s[nb][0] + s[nb][1];
            r1 += s[nb][2] + s[nb][3];
        }
        r0 += __shfl_xor_sync(0xffffffffu, r0, 1);
        r0 += __shfl_xor_sync(0xffffffffu, r0, 2);
        r1 += __shfl_xor_sync(0xffffffffu, r1, 1);
        r1 += __shfl_xor_sync(0xffffffffu, r1, 2);
        ls0 += r0; ls1 += r1;
        m0 = nm0; m1 = nm1;

        // ---- P -> bf16 hi/lo A-fragments ----
        uint32_t pah[4][4], pal[4][4];
        #pragma unroll
        for (int kp = 0; kp < 4; ++kp) {
            split_pair(s[2 * kp][0],     s[2 * kp][1],     pah[kp][0], pal[kp][0]);
            split_pair(s[2 * kp][2],     s[2 * kp][3],     pah[kp][1], pal[kp][1]);
            split_pair(s[2 * kp + 1][0], s[2 * kp + 1][1], pah[kp][2], pal[kp][2]);
            split_pair(s[2 * kp + 1][2], s[2 * kp + 1][3], pah[kp][3], pal[kp][3]);
        }

        // ---- O += P V (3-pass) ----
        {
            int rbl = (l >> 4) * 8 + (l & 7);
            int sbit = (l >> 3) & 1;
            #pragma unroll
            for (int dbp = 0; dbp < 4; ++dbp) {
                int row = dbp * 16 + rbl;
                uint32_t rbase = (uint32_t)(row * 128);
                int rx = row & 7;
                #pragma unroll
                for (int kp = 0; kp < 4; ++kp) {
                    int sl = kp * 2 + sbit;
                    uint32_t off = rbase + (uint32_t)((sl ^ rx) << 4);
                    uint32_t vh4[4], vl4[4];
                    ldm_x4(vh4, sb + AVH + off);
                    ldm_x4(vl4, sb + AVL + off);
                    mma16816(o[2 * dbp],     pah[kp], vh4);
                    mma16816(o[2 * dbp],     pah[kp], vl4);
                    mma16816(o[2 * dbp],     pal[kp], vh4);
                    mma16816(o[2 * dbp + 1], pah[kp], vh4 + 2);
                    mma16816(o[2 * dbp + 1], pah[kp], vl4 + 2);
                    mma16816(o[2 * dbp + 1], pal[kp], vh4 + 2);
                }
            }
        }
    }

    // ---- epilogue: normalize, split, write bf16 hi/lo ----
    const float inv0 = 1.0f / ls0, inv1 = 1.0f / ls1;
    uint32_t* oh0 = (uint32_t*)(ath + ((size_t)(b * TT + qr0 - q0 + q0)) * CC + h * DHH);
    uint32_t* ol0 = (uint32_t*)(atl + ((size_t)(b * TT + qr0)) * CC + h * DHH);
    uint32_t* oh1 = (uint32_t*)(ath + ((size_t)(b * TT + qr1)) * CC + h * DHH);
    uint32_t* ol1 = (uint32_t*)(atl + ((size_t)(b * TT + qr1)) * CC + h * DHH);
    #pragma unroll
    for (int db = 0; db < 8; ++db) {
        int cidx = (db * 8 + 2 * (l & 3)) >> 1;   // u32 index within 64-dim slice
        uint32_t hp, lp;
        split_pair(o[db][0] * inv0, o[db][1] * inv0, hp, lp);
        oh0[cidx] = hp; ol0[cidx] = lp;
        split_pair(o[db][2] * inv1, o[db][3] * inv1, hp, lp);
        oh1[cidx] = hp; ol1[cidx] = lp;
    }
}

// ------------------------------- launch -------------------------------------
extern "C" void kernel_launch(void* const* d_in, const int* in_sizes, int n_in,
                              void* d_out, int out_size) {
    const float* x  = (const float*)d_in[0];
    const float* Wq = (const float*)d_in[1];
    const float* bq = (const float*)d_in[2];
    const float* Wk = (const float*)d_in[3];
    const float* bk = (const float*)d_in[4];
    const float* Wv = (const float*)d_in[5];
    const float* bv = (const float*)d_in[6];
    const float* Wo = (const float*)d_in[7];
    const float* bo = (const float*)d_in[8];
    float* out = (float*)d_out;

    static int once = 0;
    if (!once) {
        cudaFuncSetAttribute(gemm_bf16x3, cudaFuncAttributeMaxDynamicSharedMemorySize, SMEM_GEMM);
        once = 1;
    }

    float *qkvp, *biasp;
    __nv_bfloat16 *xh, *xl, *wth, *wtl, *woth, *wotl, *ath, *atl;
    cudaGetSymbolAddress((void**)&xh, g_xh);
    cudaGetSymbolAddress((void**)&xl, g_xl);
    cudaGetSymbolAddress((void**)&wth, g_wth);
    cudaGetSymbolAddress((void**)&wtl, g_wtl);
    cudaGetSymbolAddress((void**)&woth, g_woth);
    cudaGetSymbolAddress((void**)&wotl, g_wotl);
    cudaGetSymbolAddress((void**)&biasp, g_bias);
    cudaGetSymbolAddress((void**)&qkvp, g_qkv);
    cudaGetSymbolAddress((void**)&ath, g_ath);
    cudaGetSymbolAddress((void**)&atl, g_atl);

    int n4 = MROWS * CC / 4;
    conv_split<<<n4 / 256, 256>>>((const float4*)x, (__nv_bfloat162*)xh, (__nv_bfloat162*)xl, n4);
    repack_qkv<<<NQKV, 256>>>(Wq, Wk, Wv, bq, bk, bv);
    repack_wo<<<CC, 256>>>(Wo);

    gemm_bf16x3<<<dim3(MROWS / 128, NQKV / 128), 256, SMEM_GEMM>>>(
        xh, xl, wth, wtl, biasp, qkvp, NQKV);

    attn_mma<<<dim3(TT / 128, BB * HH), 256>>>(qkvp, ath, atl);

    gemm_bf16x3<<<dim3(MROWS / 128, CC / 128), 256, SMEM_GEMM>>>(
        ath, atl, woth, wotl, bo, out, CC);
}

// round 5
// speedup vs baseline: 6.8820x; 1.4333x over previous
#include <cuda_runtime.h>
#include <cuda_fp16.h>
#include <math.h>
#include <stdint.h>

#define BB 4
#define TT 2048
#define CC 1024
#define HH 16
#define DHH 64
#define MROWS (BB*TT)     // 8192
#define NQKV (3*CC)       // 3072

// ------------------------------- scratch (no allocs allowed) ----------------
__device__ __half g_xh[(size_t)MROWS*CC];
__device__ __half g_xl[(size_t)MROWS*CC];
__device__ __half g_wt[(size_t)NQKV*CC];     // QKV weights, single fp16, [N][K]
__device__ __half g_wot[(size_t)CC*CC];      // Wo^T, single fp16, [N][K]
__device__ float  g_bias[NQKV];
__device__ float  g_qkv[(size_t)MROWS*NQKV];
__device__ __half g_ath[(size_t)MROWS*CC];
__device__ __half g_atl[(size_t)MROWS*CC];

// ------------------------------- PTX helpers --------------------------------
__device__ __forceinline__ uint32_t smem_u32(const void* p) {
    uint32_t a;
    asm("{ .reg .u64 t; cvta.to.shared.u64 t, %1; cvt.u32.u64 %0, t; }" : "=r"(a) : "l"(p));
    return a;
}
__device__ __forceinline__ void cp16(uint32_t dst, const void* src) {
    asm volatile("cp.async.cg.shared.global [%0], [%1], 16;" :: "r"(dst), "l"(src));
}
__device__ __forceinline__ void ldm_x4(uint32_t* r, uint32_t addr) {
    asm volatile("ldmatrix.sync.aligned.m8n8.x4.shared.b16 {%0,%1,%2,%3}, [%4];"
                 : "=r"(r[0]), "=r"(r[1]), "=r"(r[2]), "=r"(r[3]) : "r"(addr));
}
__device__ __forceinline__ void mma16816(float* d, const uint32_t* a, const uint32_t* b) {
    asm volatile(
        "mma.sync.aligned.m16n8k16.row.col.f32.f16.f16.f32 "
        "{%0,%1,%2,%3}, {%4,%5,%6,%7}, {%8,%9}, {%0,%1,%2,%3};"
        : "+f"(d[0]), "+f"(d[1]), "+f"(d[2]), "+f"(d[3])
        : "r"(a[0]), "r"(a[1]), "r"(a[2]), "r"(a[3]), "r"(b[0]), "r"(b[1]));
}
// pack two fp32 -> f16x2 (v0 in low half)
__device__ __forceinline__ uint32_t pack_f16(float v0, float v1) {
    uint32_t r;
    asm("cvt.rn.f16x2.f32 %0, %1, %2;" : "=r"(r) : "f"(v1), "f"(v0));
    return r;
}
// split pair into fp16 hi + fp16 residual
__device__ __forceinline__ void split2h(float v0, float v1, uint32_t& hp, uint32_t& lp) {
    hp = pack_f16(v0, v1);
    __half2 h = *reinterpret_cast<__half2*>(&hp);
    float2 f = __half22float2(h);
    lp = pack_f16(v0 - f.x, v1 - f.y);
}

// ------------------------------- conversion ---------------------------------
__global__ __launch_bounds__(256) void conv_split(
    const float4* __restrict__ src, uint32_t* __restrict__ hi,
    uint32_t* __restrict__ lo, int n4)
{
    int i = blockIdx.x * blockDim.x + threadIdx.x;
    if (i >= n4) return;
    float4 v = src[i];
    uint32_t h0, l0, h1, l1;
    split2h(v.x, v.y, h0, l0);
    split2h(v.z, v.w, h1, l1);
    hi[2*i] = h0; hi[2*i+1] = h1;
    lo[2*i] = l0; lo[2*i+1] = l1;
}

// repack Wq/Wk/Wv [H,C,DH] -> Wt[N=3072][K=1024] single fp16 + bias
__global__ __launch_bounds__(256) void repack_qkv(
    const float* __restrict__ Wq, const float* __restrict__ Wk, const float* __restrict__ Wv,
    const float* __restrict__ bq, const float* __restrict__ bk, const float* __restrict__ bv)
{
    int n = blockIdx.x;                    // 0..3071
    int p = n >> 10, w = n & 1023;
    int h = w >> 6, d = w & 63;
    const float* W = (p == 0) ? Wq : (p == 1) ? Wk : Wv;
    const float* bsrc = (p == 0) ? bq : (p == 1) ? bk : bv;
    for (int c = threadIdx.x; c < CC; c += 256)
        g_wt[(size_t)n * CC + c] = __float2half_rn(W[((size_t)h * CC + c) * DHH + d]);
    if (threadIdx.x == 0) g_bias[n] = bsrc[w];
}

// repack Wo [C,C] -> Wot[N=1024][K=1024] single fp16 (transpose)
__global__ __launch_bounds__(256) void repack_wo(const float* __restrict__ Wo)
{
    int n = blockIdx.x;
    for (int c = threadIdx.x; c < CC; c += 256)
        g_wot[(size_t)n * CC + c] = __float2half_rn(Wo[(size_t)c * CC + n]);
}

// ------------------------------- mma.sync GEMM ------------------------------
// C[m0:+128, n0:+128] = (Ah+Al) @ B^T + bias      (2-pass fp16, A split exact)
// A: [M x CC] fp16 hi/lo; B: [N x CC] fp16 (K contiguous rows).
#define KCH 64
#define NCH (CC / KCH)        // 16 chunks
#define TILEB 16384           // 128 rows x 128 B
#define GST (3 * TILEB)       // 48 KB / stage
#define SMEM_GEMM (2 * GST)   // 96 KB

__global__ void __launch_bounds__(256, 1) gemm_fp16x2(
    const __half* __restrict__ Ah, const __half* __restrict__ Al,
    const __half* __restrict__ B,
    const float* __restrict__ bias, float* __restrict__ C, int ldc)
{
    extern __shared__ char dsm[];
    const uint32_t sbase = smem_u32(dsm);
    const int tid = threadIdx.x;
    const int l   = tid & 31;
    const int wid = tid >> 5;
    const int wm  = wid & 1;
    const int wn  = wid >> 1;
    const int m0  = blockIdx.x * 128;
    const int n0  = blockIdx.y * 128;

    // per-thread cp.async granules: 3 tiles x 128 rows x 8 slots = 3072 / 256 thr = 12
    const __half* gptr[12];
    uint32_t soff[12];
    {
        const __half* bases[3] = {Ah, Al, B};
        #pragma unroll
        for (int it = 0; it < 12; ++it) {
            int g = it * 256 + tid;         // 0..3071
            int tile = g >> 10;             // 0..2
            int r = (g >> 3) & 127;
            int slot = g & 7;
            int row0 = (tile < 2) ? m0 : n0;
            gptr[it] = bases[tile] + (size_t)(row0 + r) * CC + slot * 8;
            soff[it] = sbase + tile * TILEB + r * 128 + ((slot ^ (r & 7)) << 4);
        }
    }

    // fragment addressing
    const int hA = l >> 4;
    uint32_t aBase[4]; int ax[4];
    #pragma unroll
    for (int i = 0; i < 4; ++i) {
        int rr = wm * 64 + (l & 15) + i * 16;
        aBase[i] = (uint32_t)(rr * 128); ax[i] = rr & 7;
    }
    const int hB = (l >> 3) & 1;
    uint32_t bBase[2]; int bx[2];
    #pragma unroll
    for (int j = 0; j < 2; ++j) {
        int rr = wn * 32 + ((l & 7) | ((l >> 4) << 3)) + j * 16;
        bBase[j] = (uint32_t)(rr * 128); bx[j] = rr & 7;
    }

    float acc[4][4][4] = {};

    #pragma unroll
    for (int it = 0; it < 12; ++it) cp16(soff[it], gptr[it]);
    asm volatile("cp.async.commit_group;" ::: "memory");

    for (int c = 0; c < NCH; ++c) {
        const uint32_t st = sbase + (c & 1) * GST;
        if (c + 1 < NCH) {
            const uint32_t nb = ((c + 1) & 1) * GST;
            const int kadv = (c + 1) * KCH;
            #pragma unroll
            for (int it = 0; it < 12; ++it) cp16(soff[it] + nb - (sbase - sbase), gptr[it] + kadv), (void)0;
            // note: soff[] holds stage-0 addresses; add nb relative to stage 0
            asm volatile("cp.async.commit_group;" ::: "memory");
            asm volatile("cp.async.wait_group 1;" ::: "memory");
        } else {
            asm volatile("cp.async.wait_group 0;" ::: "memory");
        }
        __syncthreads();

        const uint32_t sAh = st, sAl = st + TILEB, sB = st + 2 * TILEB;
        #pragma unroll
        for (int ks = 0; ks < 4; ++ks) {
            const int slA = ks * 2 + hA;
            const int slB = ks * 2 + hB;
            uint32_t ah[4][4], al_[4][4], bf[4][2];
            #pragma unroll
            for (int i = 0; i < 4; ++i) {
                uint32_t off = aBase[i] + (uint32_t)((slA ^ ax[i]) << 4);
                ldm_x4(ah[i],  sAh + off);
                ldm_x4(al_[i], sAl + off);
            }
            #pragma unroll
            for (int j = 0; j < 2; ++j) {
                uint32_t t[4];
                ldm_x4(t, sB + bBase[j] + (uint32_t)((slB ^ bx[j]) << 4));
                bf[2*j][0] = t[0]; bf[2*j][1] = t[1];
                bf[2*j+1][0] = t[2]; bf[2*j+1][1] = t[3];
            }
            #pragma unroll
            for (int i = 0; i < 4; ++i)
                #pragma unroll
                for (int j = 0; j < 4; ++j) {
                    mma16816(acc[i][j], ah[i],  bf[j]);
                    mma16816(acc[i][j], al_[i], bf[j]);
                }
        }
        __syncthreads();
    }

    #pragma unroll
    for (int i = 0; i < 4; ++i) {
        const int m = m0 + wm * 64 + i * 16 + (l >> 2);
        #pragma unroll
        for (int j = 0; j < 4; ++j) {
            const int n = n0 + wn * 32 + j * 8 + 2 * (l & 3);
            const float b0 = bias[n], b1 = bias[n + 1];
            float2 v0 = { acc[i][j][0] + b0, acc[i][j][1] + b1 };
            float2 v1 = { acc[i][j][2] + b0, acc[i][j][3] + b1 };
            *reinterpret_cast<float2*>(&C[(size_t)m * ldc + n]) = v0;
            *reinterpret_cast<float2*>(&C[(size_t)(m + 8) * ldc + n]) = v1;
        }
    }
}

// ------------------------------- mma flash attention ------------------------
// smem phases:
//  Q:  Qh[128 rows][128B] @0, Ql @16384          (32 KB)
//  KV: K[64][128B] @0, Vth[64 dims][128B] @8192, Vtl @16384   (24 KB)
#define AK  0
#define AVH 8192
#define AVL 16384
#define AQL 16384

__global__ void __launch_bounds__(256, 1) attn_mma(
    const float* __restrict__ qkv,
    __half* __restrict__ ath, __half* __restrict__ atl)
{
    __shared__ char smem[32768];
    const uint32_t sb = smem_u32(smem);
    const int tid = threadIdx.x;
    const int l   = tid & 31;
    const int wq  = tid >> 5;              // warp id: 16 queries each
    const int bh  = blockIdx.y;
    const int b   = bh >> 4, h = bh & 15;
    const int qt  = gridDim.x - 1 - blockIdx.x;
    const int q0  = qt * 128;

    const float scale = 0.03125f;
    const float* qg = qkv + ((size_t)(b * TT + q0)) * NQKV + h * DHH;
    const float* kg = qkv + ((size_t)(b * TT)) * NQKV + CC + h * DHH;
    const float* vg = qkv + ((size_t)(b * TT)) * NQKV + 2 * CC + h * DHH;

    // ---- load Q, scale, split fp16, store smem ----
    #pragma unroll
    for (int it = 0; it < 4; ++it) {
        int id = it * 256 + tid;
        int row = id >> 3, sl = id & 7;
        float4 a = *reinterpret_cast<const float4*>(qg + (size_t)row * NQKV + sl * 8);
        float4 c = *reinterpret_cast<const float4*>(qg + (size_t)row * NQKV + sl * 8 + 4);
        a.x *= scale; a.y *= scale; a.z *= scale; a.w *= scale;
        c.x *= scale; c.y *= scale; c.z *= scale; c.w *= scale;
        uint32_t hb[4], lb[4];
        split2h(a.x, a.y, hb[0], lb[0]);
        split2h(a.z, a.w, hb[1], lb[1]);
        split2h(c.x, c.y, hb[2], lb[2]);
        split2h(c.z, c.w, hb[3], lb[3]);
        uint32_t off = (uint32_t)(row * 128 + ((sl ^ (row & 7)) << 4));
        *reinterpret_cast<uint4*>(smem + off)       = make_uint4(hb[0], hb[1], hb[2], hb[3]);
        *reinterpret_cast<uint4*>(smem + AQL + off) = make_uint4(lb[0], lb[1], lb[2], lb[3]);
    }
    __syncthreads();

    // ---- ldmatrix Q fragments ----
    uint32_t qh[4][4], ql_[4][4];
    {
        int row = wq * 16 + (l & 15);
        uint32_t rbase = (uint32_t)(row * 128);
        int rx = row & 7;
        #pragma unroll
        for (int kb = 0; kb < 4; ++kb) {
            int s = kb * 2 + (l >> 4);
            uint32_t off = rbase + (uint32_t)((s ^ rx) << 4);
            ldm_x4(qh[kb],  sb + off);
            ldm_x4(ql_[kb], sb + AQL + off);
        }
    }
    __syncthreads();   // Q smem free; reuse for KV

    float o[8][4] = {};
    float m0 = -INFINITY, m1 = -INFINITY, ls0 = 0.f, ls1 = 0.f;
    const int ntiles = 2 * (qt + 1);

    // prefetch regs (tile 0)
    float kf[2][8];
    float vf[2][2][4];
    #pragma unroll
    for (int it = 0; it < 2; ++it) {
        int id = it * 256 + tid;
        int kr = id >> 3, ks = id & 7;
        *reinterpret_cast<float4*>(&kf[it][0]) =
            *reinterpret_cast<const float4*>(kg + (size_t)kr * NQKV + ks * 8);
        *reinterpret_cast<float4*>(&kf[it][4]) =
            *reinterpret_cast<const float4*>(kg + (size_t)kr * NQKV + ks * 8 + 4);
        int p = id & 31, d4 = id >> 5;
        *reinterpret_cast<float4*>(&vf[it][0][0]) =
            *reinterpret_cast<const float4*>(vg + (size_t)(2 * p) * NQKV + d4 * 4);
        *reinterpret_cast<float4*>(&vf[it][1][0]) =
            *reinterpret_cast<const float4*>(vg + (size_t)(2 * p + 1) * NQKV + d4 * 4);
    }

    const int qr0 = q0 + wq * 16 + (l >> 2);
    const int qr1 = qr0 + 8;

    for (int ti = 0; ti < ntiles; ++ti) {
        const int j0 = ti * 64;
        __syncthreads();
        // ---- convert prefetch regs -> smem (K single, V hi/lo) ----
        #pragma unroll
        for (int it = 0; it < 2; ++it) {
            int id = it * 256 + tid;
            int kr = id >> 3, ks = id & 7;
            uint32_t hb[4];
            #pragma unroll
            for (int qd = 0; qd < 4; ++qd)
                hb[qd] = pack_f16(kf[it][2 * qd], kf[it][2 * qd + 1]);
            uint32_t off = (uint32_t)(kr * 128 + ((ks ^ (kr & 7)) << 4));
            *reinterpret_cast<uint4*>(smem + AK + off) = make_uint4(hb[0], hb[1], hb[2], hb[3]);
            int p = id & 31, d4 = id >> 5;
            #pragma unroll
            for (int d = 0; d < 4; ++d) {
                uint32_t hp, lp;
                split2h(vf[it][0][d], vf[it][1][d], hp, lp);
                int drow = d4 * 4 + d;
                uint32_t off2 = (uint32_t)(drow * 128 + (((p >> 2) ^ (drow & 7)) << 4) + (p & 3) * 4);
                *reinterpret_cast<uint32_t*>(smem + AVH + off2) = hp;
                *reinterpret_cast<uint32_t*>(smem + AVL + off2) = lp;
            }
        }
        __syncthreads();

        // ---- prefetch next tile ----
        if (ti + 1 < ntiles) {
            const int jn = j0 + 64;
            #pragma unroll
            for (int it = 0; it < 2; ++it) {
                int id = it * 256 + tid;
                int kr = id >> 3, ks = id & 7;
                *reinterpret_cast<float4*>(&kf[it][0]) =
                    *reinterpret_cast<const float4*>(kg + (size_t)(jn + kr) * NQKV + ks * 8);
                *reinterpret_cast<float4*>(&kf[it][4]) =
                    *reinterpret_cast<const float4*>(kg + (size_t)(jn + kr) * NQKV + ks * 8 + 4);
                int p = id & 31, d4 = id >> 5;
                *reinterpret_cast<float4*>(&vf[it][0][0]) =
                    *reinterpret_cast<const float4*>(vg + (size_t)(jn + 2 * p) * NQKV + d4 * 4);
                *reinterpret_cast<float4*>(&vf[it][1][0]) =
                    *reinterpret_cast<const float4*>(vg + (size_t)(jn + 2 * p + 1) * NQKV + d4 * 4);
            }
        }

        // ---- S = (Qh+Ql) K^T (2-pass, K single fp16) ----
        float s[8][4] = {};
        {
            int rbl = (l >> 4) * 8 + (l & 7);
            int sbit = (l >> 3) & 1;
            #pragma unroll
            for (int nbp = 0; nbp < 4; ++nbp) {
                int row = nbp * 16 + rbl;
                uint32_t rbase = (uint32_t)(row * 128);
                int rx = row & 7;
                #pragma unroll
                for (int kb = 0; kb < 4; ++kb) {
                    int sl = kb * 2 + sbit;
                    uint32_t off = rbase + (uint32_t)((sl ^ rx) << 4);
                    uint32_t bk4[4];
                    ldm_x4(bk4, sb + AK + off);
                    mma16816(s[2 * nbp],     qh[kb],  bk4);
                    mma16816(s[2 * nbp],     ql_[kb], bk4);
                    mma16816(s[2 * nbp + 1], qh[kb],  bk4 + 2);
                    mma16816(s[2 * nbp + 1], ql_[kb], bk4 + 2);
                }
            }
        }

        // ---- causal mask (only diagonal-adjacent tiles) ----
        if (j0 >= q0) {
            #pragma unroll
            for (int nb = 0; nb < 8; ++nb) {
                int k0i = j0 + nb * 8 + 2 * (l & 3);
                if (k0i     > qr0) s[nb][0] = -INFINITY;
                if (k0i + 1 > qr0) s[nb][1] = -INFINITY;
                if (k0i     > qr1) s[nb][2] = -INFINITY;
                if (k0i + 1 > qr1) s[nb][3] = -INFINITY;
            }
        }

        // ---- online softmax ----
        float mx0 = -INFINITY, mx1 = -INFINITY;
        #pragma unroll
        for (int nb = 0; nb < 8; ++nb) {
            mx0 = fmaxf(mx0, fmaxf(s[nb][0], s[nb][1]));
            mx1 = fmaxf(mx1, fmaxf(s[nb][2], s[nb][3]));
        }
        mx0 = fmaxf(mx0, __shfl_xor_sync(0xffffffffu, mx0, 1));
        mx0 = fmaxf(mx0, __shfl_xor_sync(0xffffffffu, mx0, 2));
        mx1 = fmaxf(mx1, __shfl_xor_sync(0xffffffffu, mx1, 1));
        mx1 = fmaxf(mx1, __shfl_xor_sync(0xffffffffu, mx1, 2));
        float nm0 = fmaxf(m0, mx0), nm1 = fmaxf(m1, mx1);
        float c0 = __expf(m0 - nm0), c1 = __expf(m1 - nm1);
        ls0 *= c0; ls1 *= c1;
        #pragma unroll
        for (int db = 0; db < 8; ++db) {
            o[db][0] *= c0; o[db][1] *= c0;
            o[db][2] *= c1; o[db][3] *= c1;
        }
        float r0 = 0.f, r1 = 0.f;
        #pragma unroll
        for (int nb = 0; nb < 8; ++nb) {
            s[nb][0] = __expf(s[nb][0] - nm0);
            s[nb][1] = __expf(s[nb][1] - nm0);
            s[nb][2] = __expf(s[nb][2] - nm1);
            s[nb][3] = __expf(s[nb][3] - nm1);
            r0 += s[nb][0] + s[nb][1];
            r1 += s[nb][2] + s[nb][3];
        }
        r0 += __shfl_xor_sync(0xffffffffu, r0, 1);
        r0 += __shfl_xor_sync(0xffffffffu, r0, 2);
        r1 += __shfl_xor_sync(0xffffffffu, r1, 1);
        r1 += __shfl_xor_sync(0xffffffffu, r1, 2);
        ls0 += r0; ls1 += r1;
        m0 = nm0; m1 = nm1;

        // ---- P -> single fp16 A-fragments ----
        uint32_t pa[4][4];
        #pragma unroll
        for (int kp = 0; kp < 4; ++kp) {
            pa[kp][0] = pack_f16(s[2 * kp][0],     s[2 * kp][1]);
            pa[kp][1] = pack_f16(s[2 * kp][2],     s[2 * kp][3]);
            pa[kp][2] = pack_f16(s[2 * kp + 1][0], s[2 * kp + 1][1]);
            pa[kp][3] = pack_f16(s[2 * kp + 1][2], s[2 * kp + 1][3]);
        }

        // ---- O += P (Vh+Vl)  (2-pass, P single) ----
        {
            int rbl = (l >> 4) * 8 + (l & 7);
            int sbit = (l >> 3) & 1;
            #pragma unroll
            for (int dbp = 0; dbp < 4; ++dbp) {
                int row = dbp * 16 + rbl;
                uint32_t rbase = (uint32_t)(row * 128);
                int rx = row & 7;
                #pragma unroll
                for (int kp = 0; kp < 4; ++kp) {
                    int sl = kp * 2 + sbit;
                    uint32_t off = rbase + (uint32_t)((sl ^ rx) << 4);
                    uint32_t vh4[4], vl4[4];
                    ldm_x4(vh4, sb + AVH + off);
                    ldm_x4(vl4, sb + AVL + off);
                    mma16816(o[2 * dbp],     pa[kp], vh4);
                    mma16816(o[2 * dbp],     pa[kp], vl4);
                    mma16816(o[2 * dbp + 1], pa[kp], vh4 + 2);
                    mma16816(o[2 * dbp + 1], pa[kp], vl4 + 2);
                }
            }
        }
    }

    // ---- epilogue: normalize, split fp16 hi/lo, write ----
    const float inv0 = 1.0f / ls0, inv1 = 1.0f / ls1;
    uint32_t* oh0 = (uint32_t*)(ath + ((size_t)(b * TT + qr0)) * CC + h * DHH);
    uint32_t* ol0 = (uint32_t*)(atl + ((size_t)(b * TT + qr0)) * CC + h * DHH);
    uint32_t* oh1 = (uint32_t*)(ath + ((size_t)(b * TT + qr1)) * CC + h * DHH);
    uint32_t* ol1 = (uint32_t*)(atl + ((size_t)(b * TT + qr1)) * CC + h * DHH);
    #pragma unroll
    for (int db = 0; db < 8; ++db) {
        int cidx = (db * 8 + 2 * (l & 3)) >> 1;
        uint32_t hp, lp;
        split2h(o[db][0] * inv0, o[db][1] * inv0, hp, lp);
        oh0[cidx] = hp; ol0[cidx] = lp;
        split2h(o[db][2] * inv1, o[db][3] * inv1, hp, lp);
        oh1[cidx] = hp; ol1[cidx] = lp;
    }
}

// ------------------------------- launch -------------------------------------
extern "C" void kernel_launch(void* const* d_in, const int* in_sizes, int n_in,
                              void* d_out, int out_size) {
    const float* x  = (const float*)d_in[0];
    const float* Wq = (const float*)d_in[1];
    const float* bq = (const float*)d_in[2];
    const float* Wk = (const float*)d_in[3];
    const float* bk = (const float*)d_in[4];
    const float* Wv = (const float*)d_in[5];
    const float* bv = (const float*)d_in[6];
    const float* Wo = (const float*)d_in[7];
    const float* bo = (const float*)d_in[8];
    float* out = (float*)d_out;

    static int once = 0;
    if (!once) {
        cudaFuncSetAttribute(gemm_fp16x2, cudaFuncAttributeMaxDynamicSharedMemorySize, SMEM_GEMM);
        once = 1;
    }

    float *qkvp, *biasp;
    __half *xh, *xl, *wt, *wot, *ath, *atl;
    cudaGetSymbolAddress((void**)&xh, g_xh);
    cudaGetSymbolAddress((void**)&xl, g_xl);
    cudaGetSymbolAddress((void**)&wt, g_wt);
    cudaGetSymbolAddress((void**)&wot, g_wot);
    cudaGetSymbolAddress((void**)&biasp, g_bias);
    cudaGetSymbolAddress((void**)&qkvp, g_qkv);
    cudaGetSymbolAddress((void**)&ath, g_ath);
    cudaGetSymbolAddress((void**)&atl, g_atl);

    int n4 = MROWS * CC / 4;
    conv_split<<<n4 / 256, 256>>>((const float4*)x, (uint32_t*)xh, (uint32_t*)xl, n4);
    repack_qkv<<<NQKV, 256>>>(Wq, Wk, Wv, bq, bk, bv);
    repack_wo<<<CC, 256>>>(Wo);

    gemm_fp16x2<<<dim3(MROWS / 128, NQKV / 128), 256, SMEM_GEMM>>>(
        xh, xl, wt, biasp, qkvp, NQKV);

    attn_mma<<<dim3(TT / 128, BB * HH), 256>>>(qkvp, ath, atl);

    gemm_fp16x2<<<dim3(MROWS / 128, CC / 128), 256, SMEM_GEMM>>>(
        ath, atl, wot, bo, out, CC);
}

// round 6
// speedup vs baseline: 7.5266x; 1.0937x over previous
#include <cuda_runtime.h>
#include <cuda_fp16.h>
#include <math.h>
#include <stdint.h>

#define BB 4
#define TT 2048
#define CC 1024
#define HH 16
#define DHH 64
#define MROWS (BB*TT)     // 8192
#define NQKV (3*CC)       // 3072

// ------------------------------- scratch (no allocs allowed) ----------------
__device__ __half g_xh[(size_t)MROWS*CC];
__device__ __half g_xl[(size_t)MROWS*CC];
__device__ __half g_wt[(size_t)NQKV*CC];     // QKV weights, fp16, [N][K]
__device__ __half g_wot[(size_t)CC*CC];      // Wo^T, fp16, [N][K]
__device__ float  g_bias[NQKV];
__device__ float  g_qkv[(size_t)MROWS*NQKV];
__device__ __half g_kh [(size_t)BB*HH*TT*DHH];   // K fp16 [bh][t][d]
__device__ __half g_vth[(size_t)BB*HH*DHH*TT];   // V hi fp16 [bh][d][t]
__device__ __half g_vtl[(size_t)BB*HH*DHH*TT];   // V lo fp16 [bh][d][t]
__device__ __half g_ath[(size_t)MROWS*CC];
__device__ __half g_atl[(size_t)MROWS*CC];

// ------------------------------- PTX helpers --------------------------------
__device__ __forceinline__ uint32_t smem_u32(const void* p) {
    uint32_t a;
    asm("{ .reg .u64 t; cvta.to.shared.u64 t, %1; cvt.u32.u64 %0, t; }" : "=r"(a) : "l"(p));
    return a;
}
__device__ __forceinline__ void cp16(uint32_t dst, const void* src) {
    asm volatile("cp.async.cg.shared.global [%0], [%1], 16;" :: "r"(dst), "l"(src));
}
#define CP_COMMIT() asm volatile("cp.async.commit_group;" ::: "memory")
#define CP_WAIT1()  asm volatile("cp.async.wait_group 1;" ::: "memory")
#define CP_WAIT0()  asm volatile("cp.async.wait_group 0;" ::: "memory")
__device__ __forceinline__ void ldm_x4(uint32_t* r, uint32_t addr) {
    asm volatile("ldmatrix.sync.aligned.m8n8.x4.shared.b16 {%0,%1,%2,%3}, [%4];"
                 : "=r"(r[0]), "=r"(r[1]), "=r"(r[2]), "=r"(r[3]) : "r"(addr));
}
__device__ __forceinline__ void mma16816(float* d, const uint32_t* a, const uint32_t* b) {
    asm volatile(
        "mma.sync.aligned.m16n8k16.row.col.f32.f16.f16.f32 "
        "{%0,%1,%2,%3}, {%4,%5,%6,%7}, {%8,%9}, {%0,%1,%2,%3};"
        : "+f"(d[0]), "+f"(d[1]), "+f"(d[2]), "+f"(d[3])
        : "r"(a[0]), "r"(a[1]), "r"(a[2]), "r"(a[3]), "r"(b[0]), "r"(b[1]));
}
__device__ __forceinline__ uint32_t pack_f16(float v0, float v1) {
    uint32_t r;
    asm("cvt.rn.f16x2.f32 %0, %1, %2;" : "=r"(r) : "f"(v1), "f"(v0));
    return r;
}
__device__ __forceinline__ void split2h(float v0, float v1, uint32_t& hp, uint32_t& lp) {
    hp = pack_f16(v0, v1);
    __half2 h = *reinterpret_cast<__half2*>(&hp);
    float2 f = __half22float2(h);
    lp = pack_f16(v0 - f.x, v1 - f.y);
}

// ------------------------------- conversion ---------------------------------
__global__ __launch_bounds__(256) void conv_split(
    const float4* __restrict__ src, uint32_t* __restrict__ hi,
    uint32_t* __restrict__ lo, int n4)
{
    int i = blockIdx.x * blockDim.x + threadIdx.x;
    if (i >= n4) return;
    float4 v = src[i];
    uint32_t h0, l0, h1, l1;
    split2h(v.x, v.y, h0, l0);
    split2h(v.z, v.w, h1, l1);
    hi[2*i] = h0; hi[2*i+1] = h1;
    lo[2*i] = l0; lo[2*i+1] = l1;
}

__global__ __launch_bounds__(256) void repack_qkv(
    const float* __restrict__ Wq, const float* __restrict__ Wk, const float* __restrict__ Wv,
    const float* __restrict__ bq, const float* __restrict__ bk, const float* __restrict__ bv)
{
    int n = blockIdx.x;                    // 0..3071
    int p = n >> 10, w = n & 1023;
    int h = w >> 6, d = w & 63;
    const float* W = (p == 0) ? Wq : (p == 1) ? Wk : Wv;
    const float* bsrc = (p == 0) ? bq : (p == 1) ? bk : bv;
    for (int c = threadIdx.x; c < CC; c += 256)
        g_wt[(size_t)n * CC + c] = __float2half_rn(W[((size_t)h * CC + c) * DHH + d]);
    if (threadIdx.x == 0) g_bias[n] = bsrc[w];
}

__global__ __launch_bounds__(256) void repack_wo(const float* __restrict__ Wo)
{
    int n = blockIdx.x;
    for (int c = threadIdx.x; c < CC; c += 256)
        g_wot[(size_t)n * CC + c] = __float2half_rn(Wo[(size_t)c * CC + n]);
}

// preconvert K (fp16 [bh][t][d]) and V (fp16 hi/lo transposed [bh][d][t])
__global__ __launch_bounds__(256) void conv_kv(const float* __restrict__ qkv)
{
    const int bh = blockIdx.y;
    const int b = bh >> 4, h = bh & 15;
    const int t0 = blockIdx.x * 64;
    const int tid = threadIdx.x;
    const float* kg = qkv + (size_t)(b * TT) * NQKV + CC + h * DHH;
    const float* vg = qkv + (size_t)(b * TT) * NQKV + 2 * CC + h * DHH;
    __half* kd = g_kh + (size_t)bh * TT * DHH;

    // K: 64 rows x 8 granules
    #pragma unroll
    for (int it = 0; it < 2; ++it) {
        int id = it * 256 + tid;
        int r = id >> 3, s = id & 7;
        const float* src = kg + (size_t)(t0 + r) * NQKV + s * 8;
        float4 a = *reinterpret_cast<const float4*>(src);
        float4 c = *reinterpret_cast<const float4*>(src + 4);
        uint4 o;
        o.x = pack_f16(a.x, a.y); o.y = pack_f16(a.z, a.w);
        o.z = pack_f16(c.x, c.y); o.w = pack_f16(c.z, c.w);
        *reinterpret_cast<uint4*>(kd + (size_t)(t0 + r) * DHH + s * 8) = o;
    }

    // V transpose: d = tid&63, tgroup covers 8 t each
    const int d  = tid & 63;
    const int tg = tid >> 6;                 // 0..3
    #pragma unroll
    for (int it = 0; it < 2; ++it) {
        int tt = t0 + it * 32 + tg * 8;
        float v[8];
        #pragma unroll
        for (int j = 0; j < 8; ++j)
            v[j] = vg[(size_t)(tt + j) * NQKV + d];
        uint4 hi, lo;
        split2h(v[0], v[1], hi.x, lo.x);
        split2h(v[2], v[3], hi.y, lo.y);
        split2h(v[4], v[5], hi.z, lo.z);
        split2h(v[6], v[7], hi.w, lo.w);
        size_t off = ((size_t)bh * DHH + d) * TT + tt;
        *reinterpret_cast<uint4*>(g_vth + off) = hi;
        *reinterpret_cast<uint4*>(g_vtl + off) = lo;
    }
}

// ------------------------------- mma.sync GEMM (3-stage) --------------------
// C[m0:+128, n0:+128] = (Ah+Al) @ B^T + bias
#define KCH 64
#define NCH (CC / KCH)        // 16 chunks
#define TILEB 16384           // 128 rows x 128 B
#define GST (3 * TILEB)       // 48 KB / stage
#define SMEM_GEMM (3 * GST)   // 144 KB

__global__ void __launch_bounds__(256, 1) gemm_fp16x2(
    const __half* __restrict__ Ah, const __half* __restrict__ Al,
    const __half* __restrict__ B,
    const float* __restrict__ bias, float* __restrict__ C, int ldc)
{
    extern __shared__ char dsm[];
    const uint32_t sbase = smem_u32(dsm);
    const int tid = threadIdx.x;
    const int l   = tid & 31;
    const int wid = tid >> 5;
    const int wm  = wid & 1;
    const int wn  = wid >> 1;
    const int m0  = blockIdx.x * 128;
    const int n0  = blockIdx.y * 128;

    const __half* gptr[12];
    uint32_t srel[12];
    {
        const __half* bases[3] = {Ah, Al, B};
        #pragma unroll
        for (int it = 0; it < 12; ++it) {
            int g = it * 256 + tid;
            int tile = g >> 10;
            int r = (g >> 3) & 127;
            int slot = g & 7;
            int row0 = (tile < 2) ? m0 : n0;
            gptr[it] = bases[tile] + (size_t)(row0 + r) * CC + slot * 8;
            srel[it] = tile * TILEB + r * 128 + ((slot ^ (r & 7)) << 4);
        }
    }

    const int hA = l >> 4;
    uint32_t aBase[4]; int ax[4];
    #pragma unroll
    for (int i = 0; i < 4; ++i) {
        int rr = wm * 64 + (l & 15) + i * 16;
        aBase[i] = (uint32_t)(rr * 128); ax[i] = rr & 7;
    }
    const int hB = (l >> 3) & 1;
    uint32_t bBase[2]; int bx[2];
    #pragma unroll
    for (int j = 0; j < 2; ++j) {
        int rr = wn * 32 + ((l & 7) | ((l >> 4) << 3)) + j * 16;
        bBase[j] = (uint32_t)(rr * 128); bx[j] = rr & 7;
    }

    float acc[4][4][4] = {};

    // prologue: stages 0,1
    #pragma unroll
    for (int pc = 0; pc < 2; ++pc) {
        const uint32_t sb2 = sbase + pc * GST;
        const int kadv = pc * KCH;
        #pragma unroll
        for (int it = 0; it < 12; ++it) cp16(sb2 + srel[it], gptr[it] + kadv);
        CP_COMMIT();
    }

    int stage = 0;   // stage holding chunk c
    for (int c = 0; c < NCH; ++c) {
        if (c + 1 < NCH) CP_WAIT1(); else CP_WAIT0();
        __syncthreads();
        if (c + 2 < NCH) {
            const int sn = (stage + 2 >= 3) ? stage - 1 : stage + 2;
            const uint32_t sb2 = sbase + sn * GST;
            const int kadv = (c + 2) * KCH;
            #pragma unroll
            for (int it = 0; it < 12; ++it) cp16(sb2 + srel[it], gptr[it] + kadv);
            CP_COMMIT();
        }

        const uint32_t st = sbase + stage * GST;
        const uint32_t sAh = st, sAl = st + TILEB, sB = st + 2 * TILEB;
        #pragma unroll
        for (int ks = 0; ks < 4; ++ks) {
            const int slA = ks * 2 + hA;
            const int slB = ks * 2 + hB;
            uint32_t ah[4][4], al_[4][4], bf[4][2];
            #pragma unroll
            for (int i = 0; i < 4; ++i) {
                uint32_t off = aBase[i] + (uint32_t)((slA ^ ax[i]) << 4);
                ldm_x4(ah[i],  sAh + off);
                ldm_x4(al_[i], sAl + off);
            }
            #pragma unroll
            for (int j = 0; j < 2; ++j) {
                uint32_t t[4];
                ldm_x4(t, sB + bBase[j] + (uint32_t)((slB ^ bx[j]) << 4));
                bf[2*j][0] = t[0]; bf[2*j][1] = t[1];
                bf[2*j+1][0] = t[2]; bf[2*j+1][1] = t[3];
            }
            #pragma unroll
            for (int i = 0; i < 4; ++i)
                #pragma unroll
                for (int j = 0; j < 4; ++j) {
                    mma16816(acc[i][j], ah[i],  bf[j]);
                    mma16816(acc[i][j], al_[i], bf[j]);
                }
        }
        stage = (stage + 1 == 3) ? 0 : stage + 1;
    }

    #pragma unroll
    for (int i = 0; i < 4; ++i) {
        const int m = m0 + wm * 64 + i * 16 + (l >> 2);
        #pragma unroll
        for (int j = 0; j < 4; ++j) {
            const int n = n0 + wn * 32 + j * 8 + 2 * (l & 3);
            const float b0 = bias[n], b1 = bias[n + 1];
            float2 v0 = { acc[i][j][0] + b0, acc[i][j][1] + b1 };
            float2 v1 = { acc[i][j][2] + b0, acc[i][j][3] + b1 };
            *reinterpret_cast<float2*>(&C[(size_t)m * ldc + n]) = v0;
            *reinterpret_cast<float2*>(&C[(size_t)(m + 8) * ldc + n]) = v1;
        }
    }
}

// ------------------------------- mma flash attention (3-stage cp.async) -----
// stage (24KB): K[64 keys][128B] @0, Vth[64 dims][128B] @8192, Vtl @16384
// Q phase reuses stage memory: Qh @0 (16KB), Ql @16384 (16KB)
#define ASTG 24576
#define SMEM_ATTN (3 * ASTG)   // 72 KB
#define AQL 16384

__global__ void __launch_bounds__(256, 1) attn_mma(
    const float* __restrict__ qkv,
    __half* __restrict__ ath, __half* __restrict__ atl)
{
    extern __shared__ char smem[];
    const uint32_t sb = smem_u32(smem);
    const int tid = threadIdx.x;
    const int l   = tid & 31;
    const int wq  = tid >> 5;              // warp id: 16 queries each
    const int bh  = blockIdx.y;
    const int b   = bh >> 4, h = bh & 15;
    const int qt  = gridDim.x - 1 - blockIdx.x;
    const int q0  = qt * 128;

    const float scale = 0.03125f;
    const float* qg = qkv + ((size_t)(b * TT + q0)) * NQKV + h * DHH;

    // ---- load Q, scale, split fp16, store smem ----
    #pragma unroll
    for (int it = 0; it < 4; ++it) {
        int id = it * 256 + tid;
        int row = id >> 3, sl = id & 7;
        float4 a = *reinterpret_cast<const float4*>(qg + (size_t)row * NQKV + sl * 8);
        float4 c = *reinterpret_cast<const float4*>(qg + (size_t)row * NQKV + sl * 8 + 4);
        a.x *= scale; a.y *= scale; a.z *= scale; a.w *= scale;
        c.x *= scale; c.y *= scale; c.z *= scale; c.w *= scale;
        uint32_t hb[4], lb[4];
        split2h(a.x, a.y, hb[0], lb[0]);
        split2h(a.z, a.w, hb[1], lb[1]);
        split2h(c.x, c.y, hb[2], lb[2]);
        split2h(c.z, c.w, hb[3], lb[3]);
        uint32_t off = (uint32_t)(row * 128 + ((sl ^ (row & 7)) << 4));
        *reinterpret_cast<uint4*>(smem + off)       = make_uint4(hb[0], hb[1], hb[2], hb[3]);
        *reinterpret_cast<uint4*>(smem + AQL + off) = make_uint4(lb[0], lb[1], lb[2], lb[3]);
    }
    __syncthreads();

    uint32_t qh[4][4], ql_[4][4];
    {
        int row = wq * 16 + (l & 15);
        uint32_t rbase = (uint32_t)(row * 128);
        int rx = row & 7;
        #pragma unroll
        for (int kb = 0; kb < 4; ++kb) {
            int s = kb * 2 + (l >> 4);
            uint32_t off = rbase + (uint32_t)((s ^ rx) << 4);
            ldm_x4(qh[kb],  sb + off);
            ldm_x4(ql_[kb], sb + AQL + off);
        }
    }
    __syncthreads();   // Q smem free; stages reuse it

    // ---- per-thread cp.async descriptors (6 granules / tile) ----
    const __half* kh_b  = g_kh  + (size_t)bh * TT * DHH;
    const __half* vth_b = g_vth + (size_t)bh * DHH * TT;
    const __half* vtl_b = g_vtl + (size_t)bh * DHH * TT;
    const __half* gb[6];
    int stp[6];
    uint32_t drel[6];
    #pragma unroll
    for (int it = 0; it < 6; ++it) {
        int id = it * 256 + tid;
        int part = id >> 9;              // 0:K 1:Vh 2:Vl
        int r = (id >> 3) & 63;
        int s2 = id & 7;
        if (part == 0)      { gb[it] = kh_b  + r * DHH + s2 * 8; stp[it] = 64 * DHH; }
        else if (part == 1) { gb[it] = vth_b + (size_t)r * TT + s2 * 8; stp[it] = 64; }
        else                { gb[it] = vtl_b + (size_t)r * TT + s2 * 8; stp[it] = 64; }
        drel[it] = (uint32_t)(part * 8192 + r * 128 + ((s2 ^ (r & 7)) << 4));
    }

    float o[8][4] = {};
    float m0 = -INFINITY, m1 = -INFINITY, ls0 = 0.f, ls1 = 0.f;
    const int ntiles = 2 * (qt + 1);

    // prologue: tiles 0,1 (ntiles >= 2 always)
    #pragma unroll
    for (int pc = 0; pc < 2; ++pc) {
        const uint32_t sb2 = sb + pc * ASTG;
        #pragma unroll
        for (int it = 0; it < 6; ++it) cp16(sb2 + drel[it], gb[it] + pc * stp[it]);
        CP_COMMIT();
    }

    const int qr0 = q0 + wq * 16 + (l >> 2);
    const int qr1 = qr0 + 8;

    int stage = 0;
    for (int ti = 0; ti < ntiles; ++ti) {
        const int j0 = ti * 64;
        if (ti + 1 < ntiles) CP_WAIT1(); else CP_WAIT0();
        __syncthreads();
        if (ti + 2 < ntiles) {
            const int sn = (stage + 2 >= 3) ? stage - 1 : stage + 2;
            const uint32_t sb2 = sb + sn * ASTG;
            #pragma unroll
            for (int it = 0; it < 6; ++it) cp16(sb2 + drel[it], gb[it] + (ti + 2) * stp[it]);
            CP_COMMIT();
        }
        const uint32_t stK = sb + stage * ASTG;
        const uint32_t stVH = stK + 8192, stVL = stK + 16384;

        // ---- S = (Qh+Ql) K^T ----
        float s[8][4] = {};
        {
            int rbl = (l >> 4) * 8 + (l & 7);
            int sbit = (l >> 3) & 1;
            #pragma unroll
            for (int nbp = 0; nbp < 4; ++nbp) {
                int row = nbp * 16 + rbl;
                uint32_t rbase = (uint32_t)(row * 128);
                int rx = row & 7;
                #pragma unroll
                for (int kb = 0; kb < 4; ++kb) {
                    int sl = kb * 2 + sbit;
                    uint32_t off = rbase + (uint32_t)((sl ^ rx) << 4);
                    uint32_t bk4[4];
                    ldm_x4(bk4, stK + off);
                    mma16816(s[2 * nbp],     qh[kb],  bk4);
                    mma16816(s[2 * nbp],     ql_[kb], bk4);
                    mma16816(s[2 * nbp + 1], qh[kb],  bk4 + 2);
                    mma16816(s[2 * nbp + 1], ql_[kb], bk4 + 2);
                }
            }
        }

        // ---- causal mask ----
        if (j0 >= q0) {
            #pragma unroll
            for (int nb = 0; nb < 8; ++nb) {
                int k0i = j0 + nb * 8 + 2 * (l & 3);
                if (k0i     > qr0) s[nb][0] = -INFINITY;
                if (k0i + 1 > qr0) s[nb][1] = -INFINITY;
                if (k0i     > qr1) s[nb][2] = -INFINITY;
                if (k0i + 1 > qr1) s[nb][3] = -INFINITY;
            }
        }

        // ---- online softmax ----
        float mx0 = -INFINITY, mx1 = -INFINITY;
        #pragma unroll
        for (int nb = 0; nb < 8; ++nb) {
            mx0 = fmaxf(mx0, fmaxf(s[nb][0], s[nb][1]));
            mx1 = fmaxf(mx1, fmaxf(s[nb][2], s[nb][3]));
        }
        mx0 = fmaxf(mx0, __shfl_xor_sync(0xffffffffu, mx0, 1));
        mx0 = fmaxf(mx0, __shfl_xor_sync(0xffffffffu, mx0, 2));
        mx1 = fmaxf(mx1, __shfl_xor_sync(0xffffffffu, mx1, 1));
        mx1 = fmaxf(mx1, __shfl_xor_sync(0xffffffffu, mx1, 2));
        float nm0 = fmaxf(m0, mx0), nm1 = fmaxf(m1, mx1);
        float c0 = __expf(m0 - nm0), c1 = __expf(m1 - nm1);
        ls0 *= c0; ls1 *= c1;
        #pragma unroll
        for (int db = 0; db < 8; ++db) {
            o[db][0] *= c0; o[db][1] *= c0;
            o[db][2] *= c1; o[db][3] *= c1;
        }
        float r0 = 0.f, r1 = 0.f;
        #pragma unroll
        for (int nb = 0; nb < 8; ++nb) {
            s[nb][0] = __expf(s[nb][0] - nm0);
            s[nb][1] = __expf(s[nb][1] - nm0);
            s[nb][2] = __expf(s[nb][2] - nm1);
            s[nb][3] = __expf(s[nb][3] - nm1);
            r0 += s[nb][0] + s[nb][1];
            r1 += s[nb][2] + s[nb][3];
        }
        r0 += __shfl_xor_sync(0xffffffffu, r0, 1);
        r0 += __shfl_xor_sync(0xffffffffu, r0, 2);
        r1 += __shfl_xor_sync(0xffffffffu, r1, 1);
        r1 += __shfl_xor_sync(0xffffffffu, r1, 2);
        ls0 += r0; ls1 += r1;
        m0 = nm0; m1 = nm1;

        // ---- P -> fp16 A-fragments ----
        uint32_t pa[4][4];
        #pragma unroll
        for (int kp = 0; kp < 4; ++kp) {
            pa[kp][0] = pack_f16(s[2 * kp][0],     s[2 * kp][1]);
            pa[kp][1] = pack_f16(s[2 * kp][2],     s[2 * kp][3]);
            pa[kp][2] = pack_f16(s[2 * kp + 1][0], s[2 * kp + 1][1]);
            pa[kp][3] = pack_f16(s[2 * kp + 1][2], s[2 * kp + 1][3]);
        }

        // ---- O += P (Vh+Vl) ----
        {
            int rbl = (l >> 4) * 8 + (l & 7);
            int sbit = (l >> 3) & 1;
            #pragma unroll
            for (int dbp = 0; dbp < 4; ++dbp) {
                int row = dbp * 16 + rbl;
                uint32_t rbase = (uint32_t)(row * 128);
                int rx = row & 7;
                #pragma unroll
                for (int kp = 0; kp < 4; ++kp) {
                    int sl = kp * 2 + sbit;
                    uint32_t off = rbase + (uint32_t)((sl ^ rx) << 4);
                    uint32_t vh4[4], vl4[4];
                    ldm_x4(vh4, stVH + off);
                    ldm_x4(vl4, stVL + off);
                    mma16816(o[2 * dbp],     pa[kp], vh4);
                    mma16816(o[2 * dbp],     pa[kp], vl4);
                    mma16816(o[2 * dbp + 1], pa[kp], vh4 + 2);
                    mma16816(o[2 * dbp + 1], pa[kp], vl4 + 2);
                }
            }
        }
        stage = (stage + 1 == 3) ? 0 : stage + 1;
    }

    // ---- epilogue ----
    const float inv0 = 1.0f / ls0, inv1 = 1.0f / ls1;
    uint32_t* oh0 = (uint32_t*)(ath + ((size_t)(b * TT + qr0)) * CC + h * DHH);
    uint32_t* ol0 = (uint32_t*)(atl + ((size_t)(b * TT + qr0)) * CC + h * DHH);
    uint32_t* oh1 = (uint32_t*)(ath + ((size_t)(b * TT + qr1)) * CC + h * DHH);
    uint32_t* ol1 = (uint32_t*)(atl + ((size_t)(b * TT + qr1)) * CC + h * DHH);
    #pragma unroll
    for (int db = 0; db < 8; ++db) {
        int cidx = (db * 8 + 2 * (l & 3)) >> 1;
        uint32_t hp, lp;
        split2h(o[db][0] * inv0, o[db][1] * inv0, hp, lp);
        oh0[cidx] = hp; ol0[cidx] = lp;
        split2h(o[db][2] * inv1, o[db][3] * inv1, hp, lp);
        oh1[cidx] = hp; ol1[cidx] = lp;
    }
}

// ------------------------------- launch -------------------------------------
extern "C" void kernel_launch(void* const* d_in, const int* in_sizes, int n_in,
                              void* d_out, int out_size) {
    const float* x  = (const float*)d_in[0];
    const float* Wq = (const float*)d_in[1];
    const float* bq = (const float*)d_in[2];
    const float* Wk = (const float*)d_in[3];
    const float* bk = (const float*)d_in[4];
    const float* Wv = (const float*)d_in[5];
    const float* bv = (const float*)d_in[6];
    const float* Wo = (const float*)d_in[7];
    const float* bo = (const float*)d_in[8];
    float* out = (float*)d_out;

    cudaFuncSetAttribute(gemm_fp16x2, cudaFuncAttributeMaxDynamicSharedMemorySize, SMEM_GEMM);
    cudaFuncSetAttribute(attn_mma,    cudaFuncAttributeMaxDynamicSharedMemorySize, SMEM_ATTN);

    float *qkvp, *biasp;
    __half *xh, *xl, *wt, *wot, *ath, *atl;
    cudaGetSymbolAddress((void**)&xh, g_xh);
    cudaGetSymbolAddress((void**)&xl, g_xl);
    cudaGetSymbolAddress((void**)&wt, g_wt);
    cudaGetSymbolAddress((void**)&wot, g_wot);
    cudaGetSymbolAddress((void**)&biasp, g_bias);
    cudaGetSymbolAddress((void**)&qkvp, g_qkv);
    cudaGetSymbolAddress((void**)&ath, g_ath);
    cudaGetSymbolAddress((void**)&atl, g_atl);

    int n4 = MROWS * CC / 4;
    conv_split<<<n4 / 256, 256>>>((const float4*)x, (uint32_t*)xh, (uint32_t*)xl, n4);
    repack_qkv<<<NQKV, 256>>>(Wq, Wk, Wv, bq, bk, bv);
    repack_wo<<<CC, 256>>>(Wo);

    gemm_fp16x2<<<dim3(MROWS / 128, NQKV / 128), 256, SMEM_GEMM>>>(
        xh, xl, wt, biasp, qkvp, NQKV);

    conv_kv<<<dim3(TT / 64, BB * HH), 256>>>(qkvp);

    attn_mma<<<dim3(TT / 128, BB * HH), 256, SMEM_ATTN>>>(qkvp, ath, atl);

    gemm_fp16x2<<<dim3(MROWS / 128, CC / 128), 256, SMEM_GEMM>>>(
        ath, atl, wot, bo, out, CC);
}